// round 5
// baseline (speedup 1.0000x reference)
#include <cuda_runtime.h>
#include <cuda_bf16.h>
#include <mma.h>
#include <cstdint>

using namespace nvcuda;

#define Bq 2
#define Sq 2048
#define Eq 1024
#define Hq 16
#define Dq 64

// Scratch buffers (no cudaMalloc allowed)
__device__ float g_qkv[(size_t)Bq * Sq * 3 * Eq];     // [B*S, 3E]
__device__ float g_attn[(size_t)Bq * Sq * Eq];        // [B*S, E]
__device__ float g_xr[(size_t)Bq * Sq * Eq];          // tf32-rounded x
__device__ float g_wqkvr[(size_t)Eq * 3 * Eq];        // tf32-rounded w_qkv
__device__ float g_woutr[(size_t)Eq * Eq];            // tf32-rounded w_out

// ---------------------------------------------------------------------------
// cp.async helpers
// ---------------------------------------------------------------------------
__device__ __forceinline__ void cp16(void* dst_smem, const void* src) {
    unsigned int d = (unsigned int)__cvta_generic_to_shared(dst_smem);
    asm volatile("cp.async.cg.shared.global [%0], [%1], 16;\n" :: "r"(d), "l"(src));
}
__device__ __forceinline__ void cp_commit() {
    asm volatile("cp.async.commit_group;\n");
}
template <int N> __device__ __forceinline__ void cp_wait() {
    asm volatile("cp.async.wait_group %0;\n" :: "n"(N));
}

// ---------------------------------------------------------------------------
// Elementwise tf32 (RN) rounding pass
// ---------------------------------------------------------------------------
__global__ void round_tf32_kernel(const float* __restrict__ src,
                                  float* __restrict__ dst, int n4)
{
    int i = blockIdx.x * blockDim.x + threadIdx.x;
    if (i < n4) {
        float4 v = ((const float4*)src)[i];
        v.x = wmma::__float_to_tf32(v.x);
        v.y = wmma::__float_to_tf32(v.y);
        v.z = wmma::__float_to_tf32(v.z);
        v.w = wmma::__float_to_tf32(v.w);
        ((float4*)dst)[i] = v;
    }
}

// ---------------------------------------------------------------------------
// TF32 GEMM v3: 128x128x32 tile, 512 threads (16 warps, 4x4 grid, 32x32/warp),
// cp.async 3-stage pipeline. Inputs must already be tf32-rounded.
// ---------------------------------------------------------------------------
#define GT_M 128
#define GT_N 128
#define GT_K 32
#define A_LD 36
#define B_LD 132
#define GA_SZ (GT_M * A_LD)             // 4608
#define GB_SZ (GT_K * B_LD)             // 4224
#define STAGE_SZ (GA_SZ + GB_SZ)        // 8832 floats
#define G_STAGES 3
#define GEMM_SMEM (G_STAGES * STAGE_SZ * sizeof(float))   // 105984 B

__global__ __launch_bounds__(512) void gemm_tf32(
    const float* __restrict__ A, const float* __restrict__ B,
    float* __restrict__ C, int M, int N, int K)
{
    extern __shared__ float gsm[];

    const int tid = threadIdx.x;
    const int warp = tid >> 5;
    const int wm = warp & 3;          // 32-row slab
    const int wn = warp >> 2;         // 32-col slab
    const int brow = blockIdx.y * GT_M;
    const int bcol = blockIdx.x * GT_N;

    const int ar0 = tid >> 3;         // 0..63 (+64)
    const int ac  = (tid & 7) * 4;
    const int br0 = tid >> 5;         // 0..15 (+16)
    const int bc  = (tid & 31) * 4;

    wmma::fragment<wmma::accumulator, 16, 16, 8, float> c[2][2];
#pragma unroll
    for (int i = 0; i < 2; i++)
#pragma unroll
        for (int j = 0; j < 2; j++) wmma::fill_fragment(c[i][j], 0.f);

    const int T = K / GT_K;

    auto issue = [&](int t) {
        float* dst = gsm + (t % G_STAGES) * STAGE_SZ;
        int k0 = t * GT_K;
#pragma unroll
        for (int p = 0; p < 2; p++)
            cp16(&dst[(ar0 + p * 64) * A_LD + ac],
                 &A[(size_t)(brow + ar0 + p * 64) * K + k0 + ac]);
#pragma unroll
        for (int p = 0; p < 2; p++)
            cp16(&dst[GA_SZ + (br0 + p * 16) * B_LD + bc],
                 &B[(size_t)(k0 + br0 + p * 16) * N + bcol + bc]);
        cp_commit();
    };

    issue(0);
    issue(1);

    for (int t = 0; t < T; t++) {
        cp_wait<G_STAGES - 2>();
        __syncthreads();

        if (t + G_STAGES - 1 < T) issue(t + G_STAGES - 1);

        float* Ac = gsm + (t % G_STAGES) * STAGE_SZ;
        float* Bc = Ac + GA_SZ;
#pragma unroll
        for (int kk = 0; kk < GT_K; kk += 8) {
            wmma::fragment<wmma::matrix_a, 16, 16, 8, wmma::precision::tf32,
                           wmma::row_major> a[2];
            wmma::fragment<wmma::matrix_b, 16, 16, 8, wmma::precision::tf32,
                           wmma::row_major> bf[2];
#pragma unroll
            for (int i = 0; i < 2; i++)
                wmma::load_matrix_sync(a[i], &Ac[(wm * 32 + i * 16) * A_LD + kk], A_LD);
#pragma unroll
            for (int j = 0; j < 2; j++)
                wmma::load_matrix_sync(bf[j], &Bc[kk * B_LD + wn * 32 + j * 16], B_LD);
#pragma unroll
            for (int i = 0; i < 2; i++)
#pragma unroll
                for (int j = 0; j < 2; j++)
                    wmma::mma_sync(c[i][j], a[i], bf[j], c[i][j]);
        }
        __syncthreads();
    }

#pragma unroll
    for (int i = 0; i < 2; i++)
#pragma unroll
        for (int j = 0; j < 2; j++)
            wmma::store_matrix_sync(
                &C[(size_t)(brow + wm * 32 + i * 16) * N + bcol + wn * 32 + j * 16],
                c[i][j], N, wmma::mem_row_major);
}

// ---------------------------------------------------------------------------
// Flash attention: tf32 wmma for QK^T and PV, fused RoPE.
// CTA = (b, h, 64-query block), 256 threads = 8 warps (4 row x 2 col).
// ---------------------------------------------------------------------------
#define F_LD 72
#define F_SZ (64 * F_LD)
#define FA_SMEM (6 * F_SZ * sizeof(float))   // 110592 B

__global__ __launch_bounds__(256) void flash_attn_tc(
    const float* __restrict__ qkv,
    const float* __restrict__ fcos, const float* __restrict__ fsin,
    float* __restrict__ attn)
{
    extern __shared__ float sm[];
    float* Qs = sm;
    float* Ks = Qs + F_SZ;
    float* Vs = Ks + F_SZ;
    float* Ss = Vs + F_SZ;
    float* Ts = Ss + F_SZ;
    float* Os = Ts + F_SZ;

    const int tid = threadIdx.x;
    const int warp = tid >> 5;
    const int wr = warp & 3;
    const int wc = warp >> 2;
    const int qb = blockIdx.x;
    const int b  = blockIdx.y >> 4;
    const int h  = blockIdx.y & 15;
    const int qbase = qb * 64;
    const size_t rs3 = 3 * Eq;
    const size_t base = (size_t)b * Sq * rs3 + (size_t)h * Dq;

    const int rr = tid >> 2;
    const int qd = tid & 3;

    for (int t = tid; t < 64 * 32; t += 256) {
        int r = t >> 5, pr = t & 31;
        int sg = qbase + r;
        float2 xv = *(const float2*)&qkv[base + (size_t)sg * rs3 + 2 * pr];
        float c = fcos[sg * 32 + pr], sn = fsin[sg * 32 + pr];
        Qs[r * F_LD + 2 * pr]     = wmma::__float_to_tf32((xv.x * c - xv.y * sn) * 0.125f);
        Qs[r * F_LD + 2 * pr + 1] = wmma::__float_to_tf32((xv.x * sn + xv.y * c) * 0.125f);
    }
    for (int t = tid; t < F_SZ; t += 256) Os[t] = 0.f;

    float mrow = -1e30f, lrow = 0.f, corr = 1.f;

    for (int kt = 0; kt <= qb; ++kt) {
        const int kbase = kt * 64;

        for (int t = tid; t < 64 * 32; t += 256) {
            int r = t >> 5, pr = t & 31;
            int sg = kbase + r;
            float2 xv = *(const float2*)&qkv[base + Eq + (size_t)sg * rs3 + 2 * pr];
            float c = fcos[sg * 32 + pr], sn = fsin[sg * 32 + pr];
            Ks[r * F_LD + 2 * pr]     = wmma::__float_to_tf32(xv.x * c - xv.y * sn);
            Ks[r * F_LD + 2 * pr + 1] = wmma::__float_to_tf32(xv.x * sn + xv.y * c);
        }
        for (int t = tid; t < 64 * 16; t += 256) {
            int r = t >> 4, c4 = (t & 15) * 4;
            float4 v = *(const float4*)&qkv[base + 2 * Eq + (size_t)(kbase + r) * rs3 + c4];
            float* d = &Vs[r * F_LD + c4];
            d[0] = wmma::__float_to_tf32(v.x);
            d[1] = wmma::__float_to_tf32(v.y);
            d[2] = wmma::__float_to_tf32(v.z);
            d[3] = wmma::__float_to_tf32(v.w);
        }
        __syncthreads();

        {
            wmma::fragment<wmma::accumulator, 16, 16, 8, float> cs[2];
            wmma::fill_fragment(cs[0], 0.f);
            wmma::fill_fragment(cs[1], 0.f);
#pragma unroll
            for (int kk = 0; kk < 64; kk += 8) {
                wmma::fragment<wmma::matrix_a, 16, 16, 8, wmma::precision::tf32,
                               wmma::row_major> a;
                wmma::load_matrix_sync(a, &Qs[(wr * 16) * F_LD + kk], F_LD);
#pragma unroll
                for (int j = 0; j < 2; j++) {
                    wmma::fragment<wmma::matrix_b, 16, 16, 8, wmma::precision::tf32,
                                   wmma::col_major> bk;
                    wmma::load_matrix_sync(bk, &Ks[(wc * 32 + j * 16) * F_LD + kk], F_LD);
                    wmma::mma_sync(cs[j], a, bk, cs[j]);
                }
            }
#pragma unroll
            for (int j = 0; j < 2; j++)
                wmma::store_matrix_sync(&Ss[(wr * 16) * F_LD + wc * 32 + j * 16],
                                        cs[j], F_LD, wmma::mem_row_major);
        }
        __syncthreads();

        {
            float* srow = &Ss[rr * F_LD + qd * 16];
            float v[16];
#pragma unroll
            for (int c = 0; c < 16; c++) v[c] = srow[c];
            if (kt == qb) {
#pragma unroll
                for (int c = 0; c < 16; c++)
                    if (kbase + qd * 16 + c > qbase + rr) v[c] = -1e30f;
            }
            float mx = v[0];
#pragma unroll
            for (int c = 1; c < 16; c++) mx = fmaxf(mx, v[c]);
            mx = fmaxf(mx, __shfl_xor_sync(0xffffffffu, mx, 1));
            mx = fmaxf(mx, __shfl_xor_sync(0xffffffffu, mx, 2));
            float mn = fmaxf(mrow, mx);
            corr = __expf(mrow - mn);
            mrow = mn;
            float rsum = 0.f;
#pragma unroll
            for (int c = 0; c < 16; c++) {
                v[c] = __expf(v[c] - mn);
                rsum += v[c];
            }
            rsum += __shfl_xor_sync(0xffffffffu, rsum, 1);
            rsum += __shfl_xor_sync(0xffffffffu, rsum, 2);
            lrow = lrow * corr + rsum;
#pragma unroll
            for (int c = 0; c < 16; c++) srow[c] = wmma::__float_to_tf32(v[c]);
        }
        __syncthreads();

        {
            wmma::fragment<wmma::accumulator, 16, 16, 8, float> cd[2];
            wmma::fill_fragment(cd[0], 0.f);
            wmma::fill_fragment(cd[1], 0.f);
#pragma unroll
            for (int kk = 0; kk < 64; kk += 8) {
                wmma::fragment<wmma::matrix_a, 16, 16, 8, wmma::precision::tf32,
                               wmma::row_major> a;
                wmma::load_matrix_sync(a, &Ss[(wr * 16) * F_LD + kk], F_LD);
#pragma unroll
                for (int j = 0; j < 2; j++) {
                    wmma::fragment<wmma::matrix_b, 16, 16, 8, wmma::precision::tf32,
                                   wmma::row_major> bv;
                    wmma::load_matrix_sync(bv, &Vs[kk * F_LD + wc * 32 + j * 16], F_LD);
                    wmma::mma_sync(cd[j], a, bv, cd[j]);
                }
            }
#pragma unroll
            for (int j = 0; j < 2; j++)
                wmma::store_matrix_sync(&Ts[(wr * 16) * F_LD + wc * 32 + j * 16],
                                        cd[j], F_LD, wmma::mem_row_major);
        }
        __syncthreads();

        {
            float* orow = &Os[rr * F_LD + qd * 16];
            float* trow = &Ts[rr * F_LD + qd * 16];
#pragma unroll
            for (int c = 0; c < 16; c++) orow[c] = orow[c] * corr + trow[c];
        }
    }

    // epilogue: normalize, tf32-round (feeds out-proj GEMM directly), store
    {
        float inv = 1.f / lrow;
        float* orow = &Os[rr * F_LD + qd * 16];
        float* op = &attn[((size_t)b * Sq + qbase + rr) * Eq + h * Dq + qd * 16];
#pragma unroll
        for (int c = 0; c < 16; c += 4) {
            float4 r = make_float4(wmma::__float_to_tf32(orow[c] * inv),
                                   wmma::__float_to_tf32(orow[c + 1] * inv),
                                   wmma::__float_to_tf32(orow[c + 2] * inv),
                                   wmma::__float_to_tf32(orow[c + 3] * inv));
            *(float4*)&op[c] = r;
        }
    }
}

// ---------------------------------------------------------------------------
extern "C" void kernel_launch(void* const* d_in, const int* in_sizes, int n_in,
                              void* d_out, int out_size)
{
    const float* x     = (const float*)d_in[0];
    const float* w_qkv = (const float*)d_in[1];
    const float* w_out = (const float*)d_in[2];
    const float* fcos  = (const float*)d_in[3];
    const float* fsin  = (const float*)d_in[4];
    float* out = (float*)d_out;

    float *qkv, *attn, *xr, *wqkvr, *woutr;
    cudaGetSymbolAddress((void**)&qkv, g_qkv);
    cudaGetSymbolAddress((void**)&attn, g_attn);
    cudaGetSymbolAddress((void**)&xr, g_xr);
    cudaGetSymbolAddress((void**)&wqkvr, g_wqkvr);
    cudaGetSymbolAddress((void**)&woutr, g_woutr);

    cudaFuncSetAttribute(gemm_tf32,
                         cudaFuncAttributeMaxDynamicSharedMemorySize, GEMM_SMEM);
    cudaFuncSetAttribute(flash_attn_tc,
                         cudaFuncAttributeMaxDynamicSharedMemorySize, FA_SMEM);

    // 0) tf32 (RN) pre-rounding of GEMM inputs
    {
        int n4x = Bq * Sq * Eq / 4;
        int n4q = Eq * 3 * Eq / 4;
        int n4o = Eq * Eq / 4;
        round_tf32_kernel<<<(n4x + 255) / 256, 256>>>(x, xr, n4x);
        round_tf32_kernel<<<(n4q + 255) / 256, 256>>>(w_qkv, wqkvr, n4q);
        round_tf32_kernel<<<(n4o + 255) / 256, 256>>>(w_out, woutr, n4o);
    }

    // 1) QKV projection: [4096,1024] @ [1024,3072]
    gemm_tf32<<<dim3(3 * Eq / GT_N, Bq * Sq / GT_M), 512, GEMM_SMEM>>>(
        xr, wqkvr, qkv, Bq * Sq, 3 * Eq, Eq);

    // 2) fused RoPE + causal flash attention (tensor cores)
    flash_attn_tc<<<dim3(Sq / 64, Bq * Hq), 256, FA_SMEM>>>(qkv, fcos, fsin, attn);

    // 3) output projection: [4096,1024] @ [1024,1024]
    gemm_tf32<<<dim3(Eq / GT_N, Bq * Sq / GT_M), 512, GEMM_SMEM>>>(
        attn, woutr, out, Bq * Sq, Eq, Eq);
}

// round 6
// speedup vs baseline: 1.3172x; 1.3172x over previous
#include <cuda_runtime.h>
#include <cuda_bf16.h>
#include <mma.h>
#include <cstdint>

using namespace nvcuda;

#define Bq 2
#define Sq 2048
#define Eq 1024
#define Hq 16
#define Dq 64

// Scratch buffers (no cudaMalloc allowed)
__device__ float g_qkv[(size_t)Bq * Sq * 3 * Eq];     // [B*S, 3E]
__device__ float g_attn[(size_t)Bq * Sq * Eq];        // [B*S, E]
__device__ float g_xr[(size_t)Bq * Sq * Eq];          // tf32-rounded x
__device__ float g_wqkvr[(size_t)Eq * 3 * Eq];        // tf32-rounded w_qkv
__device__ float g_woutr[(size_t)Eq * Eq];            // tf32-rounded w_out

// ---------------------------------------------------------------------------
// cp.async helpers
// ---------------------------------------------------------------------------
__device__ __forceinline__ void cp16(void* dst_smem, const void* src) {
    unsigned int d = (unsigned int)__cvta_generic_to_shared(dst_smem);
    asm volatile("cp.async.cg.shared.global [%0], [%1], 16;\n" :: "r"(d), "l"(src));
}
__device__ __forceinline__ void cp_commit() {
    asm volatile("cp.async.commit_group;\n");
}
template <int N> __device__ __forceinline__ void cp_wait() {
    asm volatile("cp.async.wait_group %0;\n" :: "n"(N));
}

// mma.sync m16n8k8 tf32: D = A*B + C (row.col), all f32 regs (tf32 bits)
__device__ __forceinline__ void mma_tf32(float* d, const float* a, const float* b) {
    asm volatile(
        "mma.sync.aligned.m16n8k8.row.col.f32.tf32.tf32.f32 "
        "{%0,%1,%2,%3}, {%4,%5,%6,%7}, {%8,%9}, {%0,%1,%2,%3};\n"
        : "+f"(d[0]), "+f"(d[1]), "+f"(d[2]), "+f"(d[3])
        : "r"(__float_as_uint(a[0])), "r"(__float_as_uint(a[1])),
          "r"(__float_as_uint(a[2])), "r"(__float_as_uint(a[3])),
          "r"(__float_as_uint(b[0])), "r"(__float_as_uint(b[1])));
}

// ---------------------------------------------------------------------------
// Elementwise tf32 (RN) rounding pass
// ---------------------------------------------------------------------------
__global__ void round_tf32_kernel(const float* __restrict__ src,
                                  float* __restrict__ dst, int n4)
{
    int i = blockIdx.x * blockDim.x + threadIdx.x;
    if (i < n4) {
        float4 v = ((const float4*)src)[i];
        v.x = wmma::__float_to_tf32(v.x);
        v.y = wmma::__float_to_tf32(v.y);
        v.z = wmma::__float_to_tf32(v.z);
        v.w = wmma::__float_to_tf32(v.w);
        ((float4*)dst)[i] = v;
    }
}

// ---------------------------------------------------------------------------
// TF32 GEMM (unchanged from R5): 128x128x32, 512 threads, cp.async 3-stage.
// ---------------------------------------------------------------------------
#define GT_M 128
#define GT_N 128
#define GT_K 32
#define A_LD 36
#define B_LD 132
#define GA_SZ (GT_M * A_LD)
#define GB_SZ (GT_K * B_LD)
#define STAGE_SZ (GA_SZ + GB_SZ)
#define G_STAGES 3
#define GEMM_SMEM (G_STAGES * STAGE_SZ * sizeof(float))

__global__ __launch_bounds__(512) void gemm_tf32(
    const float* __restrict__ A, const float* __restrict__ B,
    float* __restrict__ C, int M, int N, int K)
{
    extern __shared__ float gsm[];

    const int tid = threadIdx.x;
    const int warp = tid >> 5;
    const int wm = warp & 3;
    const int wn = warp >> 2;
    const int brow = blockIdx.y * GT_M;
    const int bcol = blockIdx.x * GT_N;

    const int ar0 = tid >> 3;
    const int ac  = (tid & 7) * 4;
    const int br0 = tid >> 5;
    const int bc  = (tid & 31) * 4;

    wmma::fragment<wmma::accumulator, 16, 16, 8, float> c[2][2];
#pragma unroll
    for (int i = 0; i < 2; i++)
#pragma unroll
        for (int j = 0; j < 2; j++) wmma::fill_fragment(c[i][j], 0.f);

    const int T = K / GT_K;

    auto issue = [&](int t) {
        float* dst = gsm + (t % G_STAGES) * STAGE_SZ;
        int k0 = t * GT_K;
#pragma unroll
        for (int p = 0; p < 2; p++)
            cp16(&dst[(ar0 + p * 64) * A_LD + ac],
                 &A[(size_t)(brow + ar0 + p * 64) * K + k0 + ac]);
#pragma unroll
        for (int p = 0; p < 2; p++)
            cp16(&dst[GA_SZ + (br0 + p * 16) * B_LD + bc],
                 &B[(size_t)(k0 + br0 + p * 16) * N + bcol + bc]);
        cp_commit();
    };

    issue(0);
    issue(1);

    for (int t = 0; t < T; t++) {
        cp_wait<G_STAGES - 2>();
        __syncthreads();

        if (t + G_STAGES - 1 < T) issue(t + G_STAGES - 1);

        float* Ac = gsm + (t % G_STAGES) * STAGE_SZ;
        float* Bc = Ac + GA_SZ;
#pragma unroll
        for (int kk = 0; kk < GT_K; kk += 8) {
            wmma::fragment<wmma::matrix_a, 16, 16, 8, wmma::precision::tf32,
                           wmma::row_major> a[2];
            wmma::fragment<wmma::matrix_b, 16, 16, 8, wmma::precision::tf32,
                           wmma::row_major> bf[2];
#pragma unroll
            for (int i = 0; i < 2; i++)
                wmma::load_matrix_sync(a[i], &Ac[(wm * 32 + i * 16) * A_LD + kk], A_LD);
#pragma unroll
            for (int j = 0; j < 2; j++)
                wmma::load_matrix_sync(bf[j], &Bc[kk * B_LD + wn * 32 + j * 16], B_LD);
#pragma unroll
            for (int i = 0; i < 2; i++)
#pragma unroll
                for (int j = 0; j < 2; j++)
                    wmma::mma_sync(c[i][j], a[i], bf[j], c[i][j]);
        }
        __syncthreads();
    }

#pragma unroll
    for (int i = 0; i < 2; i++)
#pragma unroll
        for (int j = 0; j < 2; j++)
            wmma::store_matrix_sync(
                &C[(size_t)(brow + wm * 32 + i * 16) * N + bcol + wn * 32 + j * 16],
                c[i][j], N, wmma::mem_row_major);
}

// ---------------------------------------------------------------------------
// Register-resident flash attention (FA2 style), mma.sync m16n8k8 tf32.
// CTA = 128 q-rows x (b,h); 8 warps, 16 q-rows each. K-tile = 64 keys.
// Q in a-frags (regs, whole kernel). S in c-frags. Softmax in regs via
// quartet shuffles. P shuffled c-layout -> a-layout. O accumulates in c-frags.
// smem: Q stage (reused) then K[64][68] + V[64][72].
// ---------------------------------------------------------------------------
#define KLD 68
#define VLD 72
#define QLD 68
#define FA_SMEM ((64 * KLD + 64 * VLD) * sizeof(float))   // 35840 B

__global__ __launch_bounds__(256, 2) void flash_attn_reg(
    const float* __restrict__ qkv,
    const float* __restrict__ fcos, const float* __restrict__ fsin,
    float* __restrict__ attn)
{
    extern __shared__ float sm[];
    float* Ks = sm;                 // [64][KLD]
    float* Vs = sm + 64 * KLD;      // [64][VLD]
    float* Qstage = sm;             // [128][QLD] (overlaps K/V; used first)

    const int tid  = threadIdx.x;
    const int lane = tid & 31;
    const int wr   = tid >> 5;          // warp 0..7 -> 16-row slab
    const int g    = lane >> 2;         // group id (row within 8)
    const int j    = lane & 3;          // thread in group
    const int qi   = blockIdx.x;        // 0..15
    const int b    = blockIdx.y >> 4;
    const int h    = blockIdx.y & 15;
    const int qbase = qi * 128;
    const size_t rs3 = 3 * Eq;
    const size_t base = (size_t)b * Sq * rs3 + (size_t)h * Dq;

    // ---- stage Q (RoPE, pre-scale, tf32 RN) then load a-frags ----
    for (int t = tid; t < 128 * 32; t += 256) {
        int r = t >> 5, pr = t & 31;
        int sg = qbase + r;
        float2 xv = *(const float2*)&qkv[base + (size_t)sg * rs3 + 2 * pr];
        float c = fcos[sg * 32 + pr], sn = fsin[sg * 32 + pr];
        Qstage[r * QLD + 2 * pr]     = wmma::__float_to_tf32((xv.x * c - xv.y * sn) * 0.125f);
        Qstage[r * QLD + 2 * pr + 1] = wmma::__float_to_tf32((xv.x * sn + xv.y * c) * 0.125f);
    }
    __syncthreads();

    float qa[8][4];
    {
        const int r0 = wr * 16 + g;
#pragma unroll
        for (int kc = 0; kc < 8; kc++) {
            int col = kc * 8 + j;
            qa[kc][0] = Qstage[r0 * QLD + col];
            qa[kc][1] = Qstage[(r0 + 8) * QLD + col];
            qa[kc][2] = Qstage[r0 * QLD + col + 4];
            qa[kc][3] = Qstage[(r0 + 8) * QLD + col + 4];
        }
    }
    __syncthreads();   // Qstage region about to be reused as K/V

    float od[8][4];
#pragma unroll
    for (int n = 0; n < 8; n++)
#pragma unroll
        for (int i = 0; i < 4; i++) od[n][i] = 0.f;

    float m0 = -1e30f, m1 = -1e30f, l0 = 0.f, l1 = 0.f;

    const int wq_lo = qbase + wr * 16;      // warp's min q row
    const int wq_hi = wq_lo + 15;
    const int r0g = wq_lo + g;              // this thread's two rows
    const int r1g = r0g + 8;
    const int ntiles = 2 * qi + 2;

    for (int kt = 0; kt < ntiles; ++kt) {
        const int kbase = kt * 64;

        // ---- fill K (RoPE) and V tiles (tf32 RN) ----
        for (int t = tid; t < 64 * 32; t += 256) {
            int r = t >> 5, pr = t & 31;
            int sg = kbase + r;
            float2 xv = *(const float2*)&qkv[base + Eq + (size_t)sg * rs3 + 2 * pr];
            float c = fcos[sg * 32 + pr], sn = fsin[sg * 32 + pr];
            Ks[r * KLD + 2 * pr]     = wmma::__float_to_tf32(xv.x * c - xv.y * sn);
            Ks[r * KLD + 2 * pr + 1] = wmma::__float_to_tf32(xv.x * sn + xv.y * c);
        }
        for (int t = tid; t < 64 * 16; t += 256) {
            int r = t >> 4, c4 = (t & 15) * 4;
            float4 v = *(const float4*)&qkv[base + 2 * Eq + (size_t)(kbase + r) * rs3 + c4];
            float* d = &Vs[r * VLD + c4];
            d[0] = wmma::__float_to_tf32(v.x);
            d[1] = wmma::__float_to_tf32(v.y);
            d[2] = wmma::__float_to_tf32(v.z);
            d[3] = wmma::__float_to_tf32(v.w);
        }
        __syncthreads();

        if (kbase <= wq_hi) {
            // ---- S = Q @ K^T : 8 n-chunks x 8 k-chunks ----
            float s[8][4];
#pragma unroll
            for (int nc = 0; nc < 8; nc++) {
                s[nc][0] = s[nc][1] = s[nc][2] = s[nc][3] = 0.f;
#pragma unroll
                for (int kc = 0; kc < 8; kc++) {
                    float kb[2];
                    const float* kp = &Ks[(nc * 8 + g) * KLD + kc * 8 + j];
                    kb[0] = kp[0];
                    kb[1] = kp[4];
                    mma_tf32(s[nc], qa[kc], kb);
                }
            }

            // ---- causal mask (diagonal-overlapping tiles only) ----
            if (kbase + 63 > wq_lo) {
#pragma unroll
                for (int nc = 0; nc < 8; nc++) {
                    int c0 = kbase + nc * 8 + 2 * j;
                    if (c0 > r0g)     s[nc][0] = -1e30f;
                    if (c0 + 1 > r0g) s[nc][1] = -1e30f;
                    if (c0 > r1g)     s[nc][2] = -1e30f;
                    if (c0 + 1 > r1g) s[nc][3] = -1e30f;
                }
            }

            // ---- online softmax (rows r0g, r1g; quartet reduce) ----
            float mx0 = -1e30f, mx1 = -1e30f;
#pragma unroll
            for (int nc = 0; nc < 8; nc++) {
                mx0 = fmaxf(mx0, fmaxf(s[nc][0], s[nc][1]));
                mx1 = fmaxf(mx1, fmaxf(s[nc][2], s[nc][3]));
            }
            mx0 = fmaxf(mx0, __shfl_xor_sync(0xffffffffu, mx0, 1));
            mx0 = fmaxf(mx0, __shfl_xor_sync(0xffffffffu, mx0, 2));
            mx1 = fmaxf(mx1, __shfl_xor_sync(0xffffffffu, mx1, 1));
            mx1 = fmaxf(mx1, __shfl_xor_sync(0xffffffffu, mx1, 2));

            float mn0 = fmaxf(m0, mx0);
            float mn1 = fmaxf(m1, mx1);
            float corr0 = __expf(m0 - mn0);
            float corr1 = __expf(m1 - mn1);
            m0 = mn0; m1 = mn1;

            float sum0 = 0.f, sum1 = 0.f;
#pragma unroll
            for (int nc = 0; nc < 8; nc++) {
                s[nc][0] = __expf(s[nc][0] - mn0);
                s[nc][1] = __expf(s[nc][1] - mn0);
                s[nc][2] = __expf(s[nc][2] - mn1);
                s[nc][3] = __expf(s[nc][3] - mn1);
                sum0 += s[nc][0] + s[nc][1];
                sum1 += s[nc][2] + s[nc][3];
            }
            sum0 += __shfl_xor_sync(0xffffffffu, sum0, 1);
            sum0 += __shfl_xor_sync(0xffffffffu, sum0, 2);
            sum1 += __shfl_xor_sync(0xffffffffu, sum1, 1);
            sum1 += __shfl_xor_sync(0xffffffffu, sum1, 2);
            l0 = l0 * corr0 + sum0;
            l1 = l1 * corr1 + sum1;

            // rescale O accumulators
#pragma unroll
            for (int n = 0; n < 8; n++) {
                od[n][0] *= corr0; od[n][1] *= corr0;
                od[n][2] *= corr1; od[n][3] *= corr1;
            }

            // ---- P: c-layout -> a-layout via quartet shuffles (+ tf32 RN) ----
            const int srcA = (lane & ~3) | (j >> 1);
            const int srcB = srcA + 2;
            const bool odd = (j & 1);
#pragma unroll
            for (int kc = 0; kc < 8; kc++) {
                float p0 = wmma::__float_to_tf32(s[kc][0]);
                float p1 = wmma::__float_to_tf32(s[kc][1]);
                float p2 = wmma::__float_to_tf32(s[kc][2]);
                float p3 = wmma::__float_to_tf32(s[kc][3]);
                float t00 = __shfl_sync(0xffffffffu, p0, srcA);
                float t01 = __shfl_sync(0xffffffffu, p1, srcA);
                float t02 = __shfl_sync(0xffffffffu, p0, srcB);
                float t03 = __shfl_sync(0xffffffffu, p1, srcB);
                float t10 = __shfl_sync(0xffffffffu, p2, srcA);
                float t11 = __shfl_sync(0xffffffffu, p3, srcA);
                float t12 = __shfl_sync(0xffffffffu, p2, srcB);
                float t13 = __shfl_sync(0xffffffffu, p3, srcB);
                s[kc][0] = odd ? t01 : t00;   // a0: row g,   col j
                s[kc][1] = odd ? t11 : t10;   // a1: row g+8, col j
                s[kc][2] = odd ? t03 : t02;   // a2: row g,   col j+4
                s[kc][3] = odd ? t13 : t12;   // a3: row g+8, col j+4
            }

            // ---- O += P @ V ----
#pragma unroll
            for (int nd = 0; nd < 8; nd++) {
#pragma unroll
                for (int kc = 0; kc < 8; kc++) {
                    float vb[2];
                    const float* vp = &Vs[(kc * 8 + j) * VLD + nd * 8 + g];
                    vb[0] = vp[0];
                    vb[1] = vp[4 * VLD];
                    mma_tf32(od[nd], s[kc], vb);
                }
            }
        }
        __syncthreads();   // before next tile overwrites K/V
    }

    // ---- epilogue: normalize, tf32-round (feeds out-proj), store ----
    {
        float inv0 = 1.f / l0;
        float inv1 = 1.f / l1;
        float* op0 = &attn[((size_t)b * Sq + r0g) * Eq + h * Dq];
        float* op1 = &attn[((size_t)b * Sq + r1g) * Eq + h * Dq];
#pragma unroll
        for (int nd = 0; nd < 8; nd++) {
            int c0 = nd * 8 + 2 * j;
            float2 v0 = make_float2(wmma::__float_to_tf32(od[nd][0] * inv0),
                                    wmma::__float_to_tf32(od[nd][1] * inv0));
            float2 v1 = make_float2(wmma::__float_to_tf32(od[nd][2] * inv1),
                                    wmma::__float_to_tf32(od[nd][3] * inv1));
            *(float2*)&op0[c0] = v0;
            *(float2*)&op1[c0] = v1;
        }
    }
}

// ---------------------------------------------------------------------------
extern "C" void kernel_launch(void* const* d_in, const int* in_sizes, int n_in,
                              void* d_out, int out_size)
{
    const float* x     = (const float*)d_in[0];
    const float* w_qkv = (const float*)d_in[1];
    const float* w_out = (const float*)d_in[2];
    const float* fcos  = (const float*)d_in[3];
    const float* fsin  = (const float*)d_in[4];
    float* out = (float*)d_out;

    float *qkv, *attn, *xr, *wqkvr, *woutr;
    cudaGetSymbolAddress((void**)&qkv, g_qkv);
    cudaGetSymbolAddress((void**)&attn, g_attn);
    cudaGetSymbolAddress((void**)&xr, g_xr);
    cudaGetSymbolAddress((void**)&wqkvr, g_wqkvr);
    cudaGetSymbolAddress((void**)&woutr, g_woutr);

    cudaFuncSetAttribute(gemm_tf32,
                         cudaFuncAttributeMaxDynamicSharedMemorySize, GEMM_SMEM);

    // 0) tf32 (RN) pre-rounding of GEMM inputs
    {
        int n4x = Bq * Sq * Eq / 4;
        int n4q = Eq * 3 * Eq / 4;
        int n4o = Eq * Eq / 4;
        round_tf32_kernel<<<(n4x + 255) / 256, 256>>>(x, xr, n4x);
        round_tf32_kernel<<<(n4q + 255) / 256, 256>>>(w_qkv, wqkvr, n4q);
        round_tf32_kernel<<<(n4o + 255) / 256, 256>>>(w_out, woutr, n4o);
    }

    // 1) QKV projection: [4096,1024] @ [1024,3072]
    gemm_tf32<<<dim3(3 * Eq / GT_N, Bq * Sq / GT_M), 512, GEMM_SMEM>>>(
        xr, wqkvr, qkv, Bq * Sq, 3 * Eq, Eq);

    // 2) fused RoPE + causal flash attention (register-resident, mma.sync)
    flash_attn_reg<<<dim3(Sq / 128, Bq * Hq), 256, FA_SMEM>>>(qkv, fcos, fsin, attn);

    // 3) output projection: [4096,1024] @ [1024,1024]
    gemm_tf32<<<dim3(Eq / GT_N, Bq * Sq / GT_M), 512, GEMM_SMEM>>>(
        attn, woutr, out, Bq * Sq, Eq, Eq);
}

// round 7
// speedup vs baseline: 2.8430x; 2.1584x over previous
#include <cuda_runtime.h>
#include <cuda_bf16.h>
#include <cuda_fp16.h>
#include <mma.h>
#include <cstdint>

using namespace nvcuda;

#define Bq 2
#define Sq 2048
#define Eq 1024
#define Hq 16
#define Dq 64

// Scratch buffers (no cudaMalloc allowed)
__device__ float  g_qkv[(size_t)Bq * Sq * 3 * Eq];    // [B*S, 3E] fp32
__device__ __half g_attn[(size_t)Bq * Sq * Eq];       // [B*S, E] fp16 (feeds out-proj)
__device__ __half g_xh[(size_t)Bq * Sq * Eq];         // fp16 x
__device__ __half g_wqkvh[(size_t)Eq * 3 * Eq];       // fp16 w_qkv
__device__ __half g_wouth[(size_t)Eq * Eq];           // fp16 w_out

// ---------------------------------------------------------------------------
// cp.async helpers
// ---------------------------------------------------------------------------
__device__ __forceinline__ void cp16(void* dst_smem, const void* src) {
    unsigned int d = (unsigned int)__cvta_generic_to_shared(dst_smem);
    asm volatile("cp.async.cg.shared.global [%0], [%1], 16;\n" :: "r"(d), "l"(src));
}
__device__ __forceinline__ void cp_commit() {
    asm volatile("cp.async.commit_group;\n");
}
template <int N> __device__ __forceinline__ void cp_wait() {
    asm volatile("cp.async.wait_group %0;\n" :: "n"(N));
}

// mma.sync m16n8k8 tf32: D = A*B + C (row.col), all f32 regs (tf32 bits)
__device__ __forceinline__ void mma_tf32(float* d, const float* a, const float* b) {
    asm volatile(
        "mma.sync.aligned.m16n8k8.row.col.f32.tf32.tf32.f32 "
        "{%0,%1,%2,%3}, {%4,%5,%6,%7}, {%8,%9}, {%0,%1,%2,%3};\n"
        : "+f"(d[0]), "+f"(d[1]), "+f"(d[2]), "+f"(d[3])
        : "r"(__float_as_uint(a[0])), "r"(__float_as_uint(a[1])),
          "r"(__float_as_uint(a[2])), "r"(__float_as_uint(a[3])),
          "r"(__float_as_uint(b[0])), "r"(__float_as_uint(b[1])));
}

// ---------------------------------------------------------------------------
// Elementwise f32 -> f16 conversion pass
// ---------------------------------------------------------------------------
__global__ void f32_to_f16_kernel(const float* __restrict__ src,
                                  __half* __restrict__ dst, int n4)
{
    int i = blockIdx.x * blockDim.x + threadIdx.x;
    if (i < n4) {
        float4 v = ((const float4*)src)[i];
        __half2 a = __floats2half2_rn(v.x, v.y);
        __half2 b = __floats2half2_rn(v.z, v.w);
        ((__half2*)dst)[2 * i]     = a;
        ((__half2*)dst)[2 * i + 1] = b;
    }
}

// ---------------------------------------------------------------------------
// FP16 GEMM (f32 accum): C[M,N] = A[M,K] @ B[K,N], A/B half, C float.
// 128x128x32 tile, 512 threads (16 warps, 4x4 grid, 32x32/warp),
// wmma m16n16k16, cp.async 3-stage pipeline.
// ---------------------------------------------------------------------------
#define GT_M 128
#define GT_N 128
#define GT_K 32
#define A_LDH 40                         // halves (32 + 8 pad)
#define B_LDH 136                        // halves (128 + 8 pad)
#define GA_SZ (GT_M * A_LDH)             // 5120 halves
#define GB_SZ (GT_K * B_LDH)             // 4352 halves
#define STAGE_SZ (GA_SZ + GB_SZ)         // 9472 halves
#define G_STAGES 3
#define GEMM_SMEM (G_STAGES * STAGE_SZ * sizeof(__half))   // 56832 B

__global__ __launch_bounds__(512) void gemm_f16(
    const __half* __restrict__ A, const __half* __restrict__ B,
    float* __restrict__ C, int M, int N, int K)
{
    extern __shared__ __half gsm[];

    const int tid = threadIdx.x;
    const int warp = tid >> 5;
    const int wm = warp & 3;          // 32-row slab
    const int wn = warp >> 2;         // 32-col slab
    const int brow = blockIdx.y * GT_M;
    const int bcol = blockIdx.x * GT_N;

    // A: 128 rows x 32 halves; 512 threads x 8 halves = exactly one pass
    const int arw = tid >> 2;            // 0..127
    const int ac8 = (tid & 3) * 8;       // 0,8,16,24
    // B: 32 rows x 128 halves; 512 threads x 8 halves = one pass
    const int brw = tid >> 4;            // 0..31
    const int bc8 = (tid & 15) * 8;      // 0..120

    wmma::fragment<wmma::accumulator, 16, 16, 16, float> c[2][2];
#pragma unroll
    for (int i = 0; i < 2; i++)
#pragma unroll
        for (int j = 0; j < 2; j++) wmma::fill_fragment(c[i][j], 0.f);

    const int T = K / GT_K;

    auto issue = [&](int t) {
        __half* dst = gsm + (t % G_STAGES) * STAGE_SZ;
        int k0 = t * GT_K;
        cp16(&dst[arw * A_LDH + ac8],
             &A[(size_t)(brow + arw) * K + k0 + ac8]);
        cp16(&dst[GA_SZ + brw * B_LDH + bc8],
             &B[(size_t)(k0 + brw) * N + bcol + bc8]);
        cp_commit();
    };

    issue(0);
    issue(1);

    for (int t = 0; t < T; t++) {
        cp_wait<G_STAGES - 2>();
        __syncthreads();

        if (t + G_STAGES - 1 < T) issue(t + G_STAGES - 1);

        __half* Ac = gsm + (t % G_STAGES) * STAGE_SZ;
        __half* Bc = Ac + GA_SZ;
#pragma unroll
        for (int kk = 0; kk < GT_K; kk += 16) {
            wmma::fragment<wmma::matrix_a, 16, 16, 16, __half, wmma::row_major> a[2];
            wmma::fragment<wmma::matrix_b, 16, 16, 16, __half, wmma::row_major> bf[2];
#pragma unroll
            for (int i = 0; i < 2; i++)
                wmma::load_matrix_sync(a[i], &Ac[(wm * 32 + i * 16) * A_LDH + kk], A_LDH);
#pragma unroll
            for (int j = 0; j < 2; j++)
                wmma::load_matrix_sync(bf[j], &Bc[kk * B_LDH + wn * 32 + j * 16], B_LDH);
#pragma unroll
            for (int i = 0; i < 2; i++)
#pragma unroll
                for (int j = 0; j < 2; j++)
                    wmma::mma_sync(c[i][j], a[i], bf[j], c[i][j]);
        }
        __syncthreads();
    }

#pragma unroll
    for (int i = 0; i < 2; i++)
#pragma unroll
        for (int j = 0; j < 2; j++)
            wmma::store_matrix_sync(
                &C[(size_t)(brow + wm * 32 + i * 16) * N + bcol + wn * 32 + j * 16],
                c[i][j], N, wmma::mem_row_major);
}

// ---------------------------------------------------------------------------
// Register-resident flash attention (FA2 style), mma.sync m16n8k8 tf32.
// CTA = 128 q-rows x (b,h); 8 warps, 16 q-rows each. K-tile = 64 keys.
// Epilogue writes fp16 into g_attn (consumed by fp16 out-proj GEMM).
// ---------------------------------------------------------------------------
#define KLD 68
#define VLD 72
#define QLD 68
#define FA_SMEM ((64 * KLD + 64 * VLD) * sizeof(float))   // 35840 B

__global__ __launch_bounds__(256, 2) void flash_attn_reg(
    const float* __restrict__ qkv,
    const float* __restrict__ fcos, const float* __restrict__ fsin,
    __half* __restrict__ attn)
{
    extern __shared__ float sm[];
    float* Ks = sm;                 // [64][KLD]
    float* Vs = sm + 64 * KLD;      // [64][VLD]
    float* Qstage = sm;             // [128][QLD] (overlaps K/V; used first)

    const int tid  = threadIdx.x;
    const int lane = tid & 31;
    const int wr   = tid >> 5;
    const int g    = lane >> 2;
    const int j    = lane & 3;
    const int qi   = blockIdx.x;
    const int b    = blockIdx.y >> 4;
    const int h    = blockIdx.y & 15;
    const int qbase = qi * 128;
    const size_t rs3 = 3 * Eq;
    const size_t base = (size_t)b * Sq * rs3 + (size_t)h * Dq;

    for (int t = tid; t < 128 * 32; t += 256) {
        int r = t >> 5, pr = t & 31;
        int sg = qbase + r;
        float2 xv = *(const float2*)&qkv[base + (size_t)sg * rs3 + 2 * pr];
        float c = fcos[sg * 32 + pr], sn = fsin[sg * 32 + pr];
        Qstage[r * QLD + 2 * pr]     = wmma::__float_to_tf32((xv.x * c - xv.y * sn) * 0.125f);
        Qstage[r * QLD + 2 * pr + 1] = wmma::__float_to_tf32((xv.x * sn + xv.y * c) * 0.125f);
    }
    __syncthreads();

    float qa[8][4];
    {
        const int r0 = wr * 16 + g;
#pragma unroll
        for (int kc = 0; kc < 8; kc++) {
            int col = kc * 8 + j;
            qa[kc][0] = Qstage[r0 * QLD + col];
            qa[kc][1] = Qstage[(r0 + 8) * QLD + col];
            qa[kc][2] = Qstage[r0 * QLD + col + 4];
            qa[kc][3] = Qstage[(r0 + 8) * QLD + col + 4];
        }
    }
    __syncthreads();

    float od[8][4];
#pragma unroll
    for (int n = 0; n < 8; n++)
#pragma unroll
        for (int i = 0; i < 4; i++) od[n][i] = 0.f;

    float m0 = -1e30f, m1 = -1e30f, l0 = 0.f, l1 = 0.f;

    const int wq_lo = qbase + wr * 16;
    const int wq_hi = wq_lo + 15;
    const int r0g = wq_lo + g;
    const int r1g = r0g + 8;
    const int ntiles = 2 * qi + 2;

    for (int kt = 0; kt < ntiles; ++kt) {
        const int kbase = kt * 64;

        for (int t = tid; t < 64 * 32; t += 256) {
            int r = t >> 5, pr = t & 31;
            int sg = kbase + r;
            float2 xv = *(const float2*)&qkv[base + Eq + (size_t)sg * rs3 + 2 * pr];
            float c = fcos[sg * 32 + pr], sn = fsin[sg * 32 + pr];
            Ks[r * KLD + 2 * pr]     = wmma::__float_to_tf32(xv.x * c - xv.y * sn);
            Ks[r * KLD + 2 * pr + 1] = wmma::__float_to_tf32(xv.x * sn + xv.y * c);
        }
        for (int t = tid; t < 64 * 16; t += 256) {
            int r = t >> 4, c4 = (t & 15) * 4;
            float4 v = *(const float4*)&qkv[base + 2 * Eq + (size_t)(kbase + r) * rs3 + c4];
            float* d = &Vs[r * VLD + c4];
            d[0] = wmma::__float_to_tf32(v.x);
            d[1] = wmma::__float_to_tf32(v.y);
            d[2] = wmma::__float_to_tf32(v.z);
            d[3] = wmma::__float_to_tf32(v.w);
        }
        __syncthreads();

        if (kbase <= wq_hi) {
            float s[8][4];
#pragma unroll
            for (int nc = 0; nc < 8; nc++) {
                s[nc][0] = s[nc][1] = s[nc][2] = s[nc][3] = 0.f;
#pragma unroll
                for (int kc = 0; kc < 8; kc++) {
                    float kb[2];
                    const float* kp = &Ks[(nc * 8 + g) * KLD + kc * 8 + j];
                    kb[0] = kp[0];
                    kb[1] = kp[4];
                    mma_tf32(s[nc], qa[kc], kb);
                }
            }

            if (kbase + 63 > wq_lo) {
#pragma unroll
                for (int nc = 0; nc < 8; nc++) {
                    int c0 = kbase + nc * 8 + 2 * j;
                    if (c0 > r0g)     s[nc][0] = -1e30f;
                    if (c0 + 1 > r0g) s[nc][1] = -1e30f;
                    if (c0 > r1g)     s[nc][2] = -1e30f;
                    if (c0 + 1 > r1g) s[nc][3] = -1e30f;
                }
            }

            float mx0 = -1e30f, mx1 = -1e30f;
#pragma unroll
            for (int nc = 0; nc < 8; nc++) {
                mx0 = fmaxf(mx0, fmaxf(s[nc][0], s[nc][1]));
                mx1 = fmaxf(mx1, fmaxf(s[nc][2], s[nc][3]));
            }
            mx0 = fmaxf(mx0, __shfl_xor_sync(0xffffffffu, mx0, 1));
            mx0 = fmaxf(mx0, __shfl_xor_sync(0xffffffffu, mx0, 2));
            mx1 = fmaxf(mx1, __shfl_xor_sync(0xffffffffu, mx1, 1));
            mx1 = fmaxf(mx1, __shfl_xor_sync(0xffffffffu, mx1, 2));

            float mn0 = fmaxf(m0, mx0);
            float mn1 = fmaxf(m1, mx1);
            float corr0 = __expf(m0 - mn0);
            float corr1 = __expf(m1 - mn1);
            m0 = mn0; m1 = mn1;

            float sum0 = 0.f, sum1 = 0.f;
#pragma unroll
            for (int nc = 0; nc < 8; nc++) {
                s[nc][0] = __expf(s[nc][0] - mn0);
                s[nc][1] = __expf(s[nc][1] - mn0);
                s[nc][2] = __expf(s[nc][2] - mn1);
                s[nc][3] = __expf(s[nc][3] - mn1);
                sum0 += s[nc][0] + s[nc][1];
                sum1 += s[nc][2] + s[nc][3];
            }
            sum0 += __shfl_xor_sync(0xffffffffu, sum0, 1);
            sum0 += __shfl_xor_sync(0xffffffffu, sum0, 2);
            sum1 += __shfl_xor_sync(0xffffffffu, sum1, 1);
            sum1 += __shfl_xor_sync(0xffffffffu, sum1, 2);
            l0 = l0 * corr0 + sum0;
            l1 = l1 * corr1 + sum1;

#pragma unroll
            for (int n = 0; n < 8; n++) {
                od[n][0] *= corr0; od[n][1] *= corr0;
                od[n][2] *= corr1; od[n][3] *= corr1;
            }

            const int srcA = (lane & ~3) | (j >> 1);
            const int srcB = srcA + 2;
            const bool odd = (j & 1);
#pragma unroll
            for (int kc = 0; kc < 8; kc++) {
                float p0 = wmma::__float_to_tf32(s[kc][0]);
                float p1 = wmma::__float_to_tf32(s[kc][1]);
                float p2 = wmma::__float_to_tf32(s[kc][2]);
                float p3 = wmma::__float_to_tf32(s[kc][3]);
                float t00 = __shfl_sync(0xffffffffu, p0, srcA);
                float t01 = __shfl_sync(0xffffffffu, p1, srcA);
                float t02 = __shfl_sync(0xffffffffu, p0, srcB);
                float t03 = __shfl_sync(0xffffffffu, p1, srcB);
                float t10 = __shfl_sync(0xffffffffu, p2, srcA);
                float t11 = __shfl_sync(0xffffffffu, p3, srcA);
                float t12 = __shfl_sync(0xffffffffu, p2, srcB);
                float t13 = __shfl_sync(0xffffffffu, p3, srcB);
                s[kc][0] = odd ? t01 : t00;
                s[kc][1] = odd ? t11 : t10;
                s[kc][2] = odd ? t03 : t02;
                s[kc][3] = odd ? t13 : t12;
            }

#pragma unroll
            for (int nd = 0; nd < 8; nd++) {
#pragma unroll
                for (int kc = 0; kc < 8; kc++) {
                    float vb[2];
                    const float* vp = &Vs[(kc * 8 + j) * VLD + nd * 8 + g];
                    vb[0] = vp[0];
                    vb[1] = vp[4 * VLD];
                    mma_tf32(od[nd], s[kc], vb);
                }
            }
        }
        __syncthreads();
    }

    // ---- epilogue: normalize, convert to fp16 (feeds out-proj), store ----
    {
        float inv0 = 1.f / l0;
        float inv1 = 1.f / l1;
        __half* op0 = &attn[((size_t)b * Sq + r0g) * Eq + h * Dq];
        __half* op1 = &attn[((size_t)b * Sq + r1g) * Eq + h * Dq];
#pragma unroll
        for (int nd = 0; nd < 8; nd++) {
            int c0 = nd * 8 + 2 * j;
            __half2 v0 = __floats2half2_rn(od[nd][0] * inv0, od[nd][1] * inv0);
            __half2 v1 = __floats2half2_rn(od[nd][2] * inv1, od[nd][3] * inv1);
            *(__half2*)&op0[c0] = v0;
            *(__half2*)&op1[c0] = v1;
        }
    }
}

// ---------------------------------------------------------------------------
extern "C" void kernel_launch(void* const* d_in, const int* in_sizes, int n_in,
                              void* d_out, int out_size)
{
    const float* x     = (const float*)d_in[0];
    const float* w_qkv = (const float*)d_in[1];
    const float* w_out = (const float*)d_in[2];
    const float* fcos  = (const float*)d_in[3];
    const float* fsin  = (const float*)d_in[4];
    float* out = (float*)d_out;

    float *qkv;
    __half *attn, *xh, *wqkvh, *wouth;
    cudaGetSymbolAddress((void**)&qkv, g_qkv);
    cudaGetSymbolAddress((void**)&attn, g_attn);
    cudaGetSymbolAddress((void**)&xh, g_xh);
    cudaGetSymbolAddress((void**)&wqkvh, g_wqkvh);
    cudaGetSymbolAddress((void**)&wouth, g_wouth);

    cudaFuncSetAttribute(gemm_f16,
                         cudaFuncAttributeMaxDynamicSharedMemorySize, GEMM_SMEM);

    // 0) fp16 (RN) conversion of GEMM inputs
    {
        int n4x = Bq * Sq * Eq / 4;
        int n4q = Eq * 3 * Eq / 4;
        int n4o = Eq * Eq / 4;
        f32_to_f16_kernel<<<(n4x + 255) / 256, 256>>>(x, xh, n4x);
        f32_to_f16_kernel<<<(n4q + 255) / 256, 256>>>(w_qkv, wqkvh, n4q);
        f32_to_f16_kernel<<<(n4o + 255) / 256, 256>>>(w_out, wouth, n4o);
    }

    // 1) QKV projection: [4096,1024] @ [1024,3072] (fp16 HMMA, f32 accum)
    gemm_f16<<<dim3(3 * Eq / GT_N, Bq * Sq / GT_M), 512, GEMM_SMEM>>>(
        xh, wqkvh, qkv, Bq * Sq, 3 * Eq, Eq);

    // 2) fused RoPE + causal flash attention (register-resident, mma.sync)
    flash_attn_reg<<<dim3(Sq / 128, Bq * Hq), 256, FA_SMEM>>>(qkv, fcos, fsin, attn);

    // 3) output projection: [4096,1024] @ [1024,1024] (fp16 HMMA, f32 accum)
    gemm_f16<<<dim3(Eq / GT_N, Bq * Sq / GT_M), 512, GEMM_SMEM>>>(
        attn, wouth, out, Bq * Sq, Eq, Eq);
}

// round 9
// speedup vs baseline: 3.5800x; 1.2592x over previous
#include <cuda_runtime.h>
#include <cuda_bf16.h>
#include <cuda_fp16.h>
#include <mma.h>
#include <cstdint>
#include <type_traits>

using namespace nvcuda;

#define Bq 2
#define Sq 2048
#define Eq 1024
#define Hq 16
#define Dq 64

// Scratch buffers (no cudaMalloc allowed)
__device__ __half g_qkv[(size_t)Bq * Sq * 3 * Eq];    // [B*S, 3E] fp16
__device__ __half g_attn[(size_t)Bq * Sq * Eq];       // [B*S, E] fp16
__device__ __half g_xh[(size_t)Bq * Sq * Eq];         // fp16 x
__device__ __half g_wqkvh[(size_t)Eq * 3 * Eq];       // fp16 w_qkv
__device__ __half g_wouth[(size_t)Eq * Eq];           // fp16 w_out

// ---------------------------------------------------------------------------
// helpers
// ---------------------------------------------------------------------------
__device__ __forceinline__ void cp16(void* dst_smem, const void* src) {
    unsigned int d = (unsigned int)__cvta_generic_to_shared(dst_smem);
    asm volatile("cp.async.cg.shared.global [%0], [%1], 16;\n" :: "r"(d), "l"(src));
}
__device__ __forceinline__ void cp_commit() {
    asm volatile("cp.async.commit_group;\n");
}
template <int N> __device__ __forceinline__ void cp_wait() {
    asm volatile("cp.async.wait_group %0;\n" :: "n"(N));
}

// mma m16n8k16 fp16 inputs, f32 accum
__device__ __forceinline__ void mma_f16(float* d, const uint32_t* a,
                                        uint32_t b0, uint32_t b1) {
    asm volatile(
        "mma.sync.aligned.m16n8k16.row.col.f32.f16.f16.f32 "
        "{%0,%1,%2,%3}, {%4,%5,%6,%7}, {%8,%9}, {%0,%1,%2,%3};\n"
        : "+f"(d[0]), "+f"(d[1]), "+f"(d[2]), "+f"(d[3])
        : "r"(a[0]), "r"(a[1]), "r"(a[2]), "r"(a[3]), "r"(b0), "r"(b1));
}

__device__ __forceinline__ void ldsm_x4_trans(unsigned int addr,
    uint32_t& r0, uint32_t& r1, uint32_t& r2, uint32_t& r3) {
    asm volatile(
        "ldmatrix.sync.aligned.m8n8.x4.trans.shared.b16 {%0,%1,%2,%3}, [%4];\n"
        : "=r"(r0), "=r"(r1), "=r"(r2), "=r"(r3) : "r"(addr));
}

__device__ __forceinline__ uint32_t packh2(float lo, float hi) {
    __half2 h = __floats2half2_rn(lo, hi);
    return *(uint32_t*)&h;
}

// ---------------------------------------------------------------------------
// Elementwise f32 -> f16 conversion pass
// ---------------------------------------------------------------------------
__global__ void f32_to_f16_kernel(const float* __restrict__ src,
                                  __half* __restrict__ dst, int n4)
{
    int i = blockIdx.x * blockDim.x + threadIdx.x;
    if (i < n4) {
        float4 v = ((const float4*)src)[i];
        ((__half2*)dst)[2 * i]     = __floats2half2_rn(v.x, v.y);
        ((__half2*)dst)[2 * i + 1] = __floats2half2_rn(v.z, v.w);
    }
}

// ---------------------------------------------------------------------------
// FP16 GEMM (f32 accum): C[M,N] = A[M,K] @ B[K,N]. OutT = float or __half.
// 128x128x32 tile, 512 threads, wmma m16n16k16, cp.async 3-stage.
// ---------------------------------------------------------------------------
#define GT_M 128
#define GT_N 128
#define GT_K 32
#define A_LDH 40
#define B_LDH 136
#define GA_SZ (GT_M * A_LDH)
#define GB_SZ (GT_K * B_LDH)
#define STAGE_SZ (GA_SZ + GB_SZ)
#define G_STAGES 3
#define GEMM_SMEM (G_STAGES * STAGE_SZ * sizeof(__half))   // 56832 B
#define C_STAGE_LD 20   // floats; MUST be multiple of 4 for wmma f32 store

template <typename OutT>
__global__ __launch_bounds__(512) void gemm_f16(
    const __half* __restrict__ A, const __half* __restrict__ B,
    OutT* __restrict__ C, int M, int N, int K)
{
    extern __shared__ __half gsm[];

    const int tid = threadIdx.x;
    const int warp = tid >> 5;
    const int lane = tid & 31;
    const int wm = warp & 3;
    const int wn = warp >> 2;
    const int brow = blockIdx.y * GT_M;
    const int bcol = blockIdx.x * GT_N;

    const int arw = tid >> 2;
    const int ac8 = (tid & 3) * 8;
    const int brw = tid >> 4;
    const int bc8 = (tid & 15) * 8;

    wmma::fragment<wmma::accumulator, 16, 16, 16, float> c[2][2];
#pragma unroll
    for (int i = 0; i < 2; i++)
#pragma unroll
        for (int j = 0; j < 2; j++) wmma::fill_fragment(c[i][j], 0.f);

    const int T = K / GT_K;

    auto issue = [&](int t) {
        __half* dst = gsm + (t % G_STAGES) * STAGE_SZ;
        int k0 = t * GT_K;
        cp16(&dst[arw * A_LDH + ac8], &A[(size_t)(brow + arw) * K + k0 + ac8]);
        cp16(&dst[GA_SZ + brw * B_LDH + bc8],
             &B[(size_t)(k0 + brw) * N + bcol + bc8]);
        cp_commit();
    };

    issue(0);
    issue(1);

    for (int t = 0; t < T; t++) {
        cp_wait<G_STAGES - 2>();
        __syncthreads();

        if (t + G_STAGES - 1 < T) issue(t + G_STAGES - 1);

        __half* Ac = gsm + (t % G_STAGES) * STAGE_SZ;
        __half* Bc = Ac + GA_SZ;
#pragma unroll
        for (int kk = 0; kk < GT_K; kk += 16) {
            wmma::fragment<wmma::matrix_a, 16, 16, 16, __half, wmma::row_major> a[2];
            wmma::fragment<wmma::matrix_b, 16, 16, 16, __half, wmma::row_major> bf[2];
#pragma unroll
            for (int i = 0; i < 2; i++)
                wmma::load_matrix_sync(a[i], &Ac[(wm * 32 + i * 16) * A_LDH + kk], A_LDH);
#pragma unroll
            for (int j = 0; j < 2; j++)
                wmma::load_matrix_sync(bf[j], &Bc[kk * B_LDH + wn * 32 + j * 16], B_LDH);
#pragma unroll
            for (int i = 0; i < 2; i++)
#pragma unroll
                for (int j = 0; j < 2; j++)
                    wmma::mma_sync(c[i][j], a[i], bf[j], c[i][j]);
        }
        __syncthreads();
    }

    if constexpr (std::is_same<OutT, float>::value) {
#pragma unroll
        for (int i = 0; i < 2; i++)
#pragma unroll
            for (int j = 0; j < 2; j++)
                wmma::store_matrix_sync(
                    &C[(size_t)(brow + wm * 32 + i * 16) * N + bcol + wn * 32 + j * 16],
                    c[i][j], N, wmma::mem_row_major);
    } else {
        // stage f32 c-frags through smem, emit fp16 (per-warp region, ld=20)
        float* stage = (float*)gsm + warp * (16 * C_STAGE_LD);
        const int r = lane >> 1;
        const int c0 = (lane & 1) * 8;
#pragma unroll
        for (int i = 0; i < 2; i++)
#pragma unroll
            for (int j = 0; j < 2; j++) {
                wmma::store_matrix_sync(stage, c[i][j], C_STAGE_LD,
                                        wmma::mem_row_major);
                __syncwarp();
                const float* sp = stage + r * C_STAGE_LD + c0;
                __half2 h[4];
#pragma unroll
                for (int q = 0; q < 4; q++)
                    h[q] = __floats2half2_rn(sp[2 * q], sp[2 * q + 1]);
                *(uint4*)&C[(size_t)(brow + wm * 32 + i * 16 + r) * N +
                            bcol + wn * 32 + j * 16 + c0] = *(uint4*)h;
                __syncwarp();
            }
    }
}

// ---------------------------------------------------------------------------
// Register-resident flash attention, fp16 mma m16n8k16.
// CTA = 128 q-rows x (b,h); 8 warps, 16 q-rows each. K-tile = 64 keys.
// Q a-frags packed fp16 (regs). S/O accumulate f32 c-frags. P: c-frag
// layout == a-frag layout (no shuffle). V b-frags via ldmatrix.x4.trans.
// ---------------------------------------------------------------------------
#define QLDH 72
#define KLDH 72
#define VLDH 72
#define FA_SMEM (128 * QLDH * sizeof(__half))   // 18432 B (Q stage; K+V overlap)

__global__ __launch_bounds__(256, 2) void flash_attn_f16(
    const __half* __restrict__ qkv,
    const float* __restrict__ fcos, const float* __restrict__ fsin,
    __half* __restrict__ attn)
{
    extern __shared__ __half smh[];
    __half* Ks = smh;                  // [64][KLDH]
    __half* Vs = smh + 64 * KLDH;      // [64][VLDH]
    __half* Qstage = smh;              // [128][QLDH] (overlaps; used first)

    const int tid  = threadIdx.x;
    const int lane = tid & 31;
    const int wr   = tid >> 5;
    const int g    = lane >> 2;
    const int j    = lane & 3;
    const int qi   = blockIdx.x;
    const int b    = blockIdx.y >> 4;
    const int h    = blockIdx.y & 15;
    const int qbase = qi * 128;
    const size_t rs3 = 3 * Eq;
    const size_t base = (size_t)b * Sq * rs3 + (size_t)h * Dq;

    // ---- stage Q (RoPE fp32, pre-scale, -> fp16) ----
    for (int t = tid; t < 128 * 32; t += 256) {
        int r = t >> 5, pr = t & 31;
        int sg = qbase + r;
        float2 xv = __half22float2(*(const __half2*)&qkv[base + (size_t)sg * rs3 + 2 * pr]);
        float c = fcos[sg * 32 + pr], sn = fsin[sg * 32 + pr];
        *(__half2*)&Qstage[r * QLDH + 2 * pr] =
            __floats2half2_rn((xv.x * c - xv.y * sn) * 0.125f,
                              (xv.x * sn + xv.y * c) * 0.125f);
    }
    __syncthreads();

    uint32_t qa[4][4];
    {
        const int r0 = wr * 16 + g;
#pragma unroll
        for (int kc = 0; kc < 4; kc++) {
            int col = kc * 16 + 2 * j;
            qa[kc][0] = *(const uint32_t*)&Qstage[r0 * QLDH + col];
            qa[kc][1] = *(const uint32_t*)&Qstage[(r0 + 8) * QLDH + col];
            qa[kc][2] = *(const uint32_t*)&Qstage[r0 * QLDH + col + 8];
            qa[kc][3] = *(const uint32_t*)&Qstage[(r0 + 8) * QLDH + col + 8];
        }
    }
    __syncthreads();   // Qstage about to be reused as K/V

    float od[8][4];
#pragma unroll
    for (int n = 0; n < 8; n++)
#pragma unroll
        for (int i = 0; i < 4; i++) od[n][i] = 0.f;

    float m0 = -1e30f, m1 = -1e30f, l0 = 0.f, l1 = 0.f;

    const int wq_lo = qbase + wr * 16;
    const int wq_hi = wq_lo + 15;
    const int r0g = wq_lo + g;
    const int r1g = r0g + 8;
    const int ntiles = 2 * qi + 2;

    // ldmatrix per-lane offsets: m = lane>>3 selects 8x8 tile
    const int lm_m  = lane >> 3;
    const int lm_rr = lane & 7;
    const int lm_keyoff = (lm_m & 1) * 8 + lm_rr;
    const int lm_dimoff = (lm_m >> 1) * 8;

    for (int kt = 0; kt < ntiles; ++kt) {
        const int kbase = kt * 64;

        // ---- fill K (RoPE fp32 -> fp16) ----
        for (int t = tid; t < 64 * 32; t += 256) {
            int r = t >> 5, pr = t & 31;
            int sg = kbase + r;
            float2 xv = __half22float2(
                *(const __half2*)&qkv[base + Eq + (size_t)sg * rs3 + 2 * pr]);
            float c = fcos[sg * 32 + pr], sn = fsin[sg * 32 + pr];
            *(__half2*)&Ks[r * KLDH + 2 * pr] =
                __floats2half2_rn(xv.x * c - xv.y * sn, xv.x * sn + xv.y * c);
        }
        // ---- fill V (straight fp16 copy) ----
        for (int t = tid; t < 64 * 16; t += 256) {
            int r = t >> 4, c4 = (t & 15) * 4;
            *(uint2*)&Vs[r * VLDH + c4] =
                *(const uint2*)&qkv[base + 2 * Eq + (size_t)(kbase + r) * rs3 + c4];
        }
        __syncthreads();

        if (kbase <= wq_hi) {
            // ---- S = Q @ K^T : 8 n-chunks x 4 k16-chunks ----
            float s[8][4];
#pragma unroll
            for (int nc = 0; nc < 8; nc++) {
                s[nc][0] = s[nc][1] = s[nc][2] = s[nc][3] = 0.f;
                const __half* krow = &Ks[(nc * 8 + g) * KLDH + 2 * j];
#pragma unroll
                for (int kc = 0; kc < 4; kc++) {
                    uint32_t kb0 = *(const uint32_t*)&krow[kc * 16];
                    uint32_t kb1 = *(const uint32_t*)&krow[kc * 16 + 8];
                    mma_f16(s[nc], qa[kc], kb0, kb1);
                }
            }

            // ---- causal mask ----
            if (kbase + 63 > wq_lo) {
#pragma unroll
                for (int nc = 0; nc < 8; nc++) {
                    int c0 = kbase + nc * 8 + 2 * j;
                    if (c0 > r0g)     s[nc][0] = -1e30f;
                    if (c0 + 1 > r0g) s[nc][1] = -1e30f;
                    if (c0 > r1g)     s[nc][2] = -1e30f;
                    if (c0 + 1 > r1g) s[nc][3] = -1e30f;
                }
            }

            // ---- online softmax ----
            float mx0 = -1e30f, mx1 = -1e30f;
#pragma unroll
            for (int nc = 0; nc < 8; nc++) {
                mx0 = fmaxf(mx0, fmaxf(s[nc][0], s[nc][1]));
                mx1 = fmaxf(mx1, fmaxf(s[nc][2], s[nc][3]));
            }
            mx0 = fmaxf(mx0, __shfl_xor_sync(0xffffffffu, mx0, 1));
            mx0 = fmaxf(mx0, __shfl_xor_sync(0xffffffffu, mx0, 2));
            mx1 = fmaxf(mx1, __shfl_xor_sync(0xffffffffu, mx1, 1));
            mx1 = fmaxf(mx1, __shfl_xor_sync(0xffffffffu, mx1, 2));

            float mn0 = fmaxf(m0, mx0);
            float mn1 = fmaxf(m1, mx1);
            float corr0 = __expf(m0 - mn0);
            float corr1 = __expf(m1 - mn1);
            m0 = mn0; m1 = mn1;

            float sum0 = 0.f, sum1 = 0.f;
#pragma unroll
            for (int nc = 0; nc < 8; nc++) {
                s[nc][0] = __expf(s[nc][0] - mn0);
                s[nc][1] = __expf(s[nc][1] - mn0);
                s[nc][2] = __expf(s[nc][2] - mn1);
                s[nc][3] = __expf(s[nc][3] - mn1);
                sum0 += s[nc][0] + s[nc][1];
                sum1 += s[nc][2] + s[nc][3];
            }
            sum0 += __shfl_xor_sync(0xffffffffu, sum0, 1);
            sum0 += __shfl_xor_sync(0xffffffffu, sum0, 2);
            sum1 += __shfl_xor_sync(0xffffffffu, sum1, 1);
            sum1 += __shfl_xor_sync(0xffffffffu, sum1, 2);
            l0 = l0 * corr0 + sum0;
            l1 = l1 * corr1 + sum1;

#pragma unroll
            for (int n = 0; n < 8; n++) {
                od[n][0] *= corr0; od[n][1] *= corr0;
                od[n][2] *= corr1; od[n][3] *= corr1;
            }

            // ---- P c-frags -> fp16 a-frags (no shuffle: layouts match) ----
            uint32_t pa[4][4];
#pragma unroll
            for (int kc = 0; kc < 4; kc++) {
                pa[kc][0] = packh2(s[2 * kc][0],     s[2 * kc][1]);
                pa[kc][1] = packh2(s[2 * kc][2],     s[2 * kc][3]);
                pa[kc][2] = packh2(s[2 * kc + 1][0], s[2 * kc + 1][1]);
                pa[kc][3] = packh2(s[2 * kc + 1][2], s[2 * kc + 1][3]);
            }

            // ---- O += P @ V (V b-frags via ldmatrix.x4.trans) ----
#pragma unroll
            for (int nd2 = 0; nd2 < 4; nd2++) {
#pragma unroll
                for (int kc = 0; kc < 4; kc++) {
                    unsigned int addr = (unsigned int)__cvta_generic_to_shared(
                        &Vs[(kc * 16 + lm_keyoff) * VLDH + nd2 * 16 + lm_dimoff]);
                    uint32_t b0, b1, b2, b3;
                    ldsm_x4_trans(addr, b0, b1, b2, b3);
                    mma_f16(od[2 * nd2],     pa[kc], b0, b1);
                    mma_f16(od[2 * nd2 + 1], pa[kc], b2, b3);
                }
            }
        }
        __syncthreads();
    }

    // ---- epilogue: normalize, fp16, store ----
    {
        float inv0 = 1.f / l0;
        float inv1 = 1.f / l1;
        __half* op0 = &attn[((size_t)b * Sq + r0g) * Eq + h * Dq];
        __half* op1 = &attn[((size_t)b * Sq + r1g) * Eq + h * Dq];
#pragma unroll
        for (int nd = 0; nd < 8; nd++) {
            int c0 = nd * 8 + 2 * j;
            *(__half2*)&op0[c0] = __floats2half2_rn(od[nd][0] * inv0, od[nd][1] * inv0);
            *(__half2*)&op1[c0] = __floats2half2_rn(od[nd][2] * inv1, od[nd][3] * inv1);
        }
    }
}

// ---------------------------------------------------------------------------
extern "C" void kernel_launch(void* const* d_in, const int* in_sizes, int n_in,
                              void* d_out, int out_size)
{
    const float* x     = (const float*)d_in[0];
    const float* w_qkv = (const float*)d_in[1];
    const float* w_out = (const float*)d_in[2];
    const float* fcos  = (const float*)d_in[3];
    const float* fsin  = (const float*)d_in[4];
    float* out = (float*)d_out;

    __half *qkv, *attn, *xh, *wqkvh, *wouth;
    cudaGetSymbolAddress((void**)&qkv, g_qkv);
    cudaGetSymbolAddress((void**)&attn, g_attn);
    cudaGetSymbolAddress((void**)&xh, g_xh);
    cudaGetSymbolAddress((void**)&wqkvh, g_wqkvh);
    cudaGetSymbolAddress((void**)&wouth, g_wouth);

    cudaFuncSetAttribute(gemm_f16<__half>,
                         cudaFuncAttributeMaxDynamicSharedMemorySize, GEMM_SMEM);
    cudaFuncSetAttribute(gemm_f16<float>,
                         cudaFuncAttributeMaxDynamicSharedMemorySize, GEMM_SMEM);

    // 0) fp16 conversion of GEMM inputs
    {
        int n4x = Bq * Sq * Eq / 4;
        int n4q = Eq * 3 * Eq / 4;
        int n4o = Eq * Eq / 4;
        f32_to_f16_kernel<<<(n4x + 255) / 256, 256>>>(x, xh, n4x);
        f32_to_f16_kernel<<<(n4q + 255) / 256, 256>>>(w_qkv, wqkvh, n4q);
        f32_to_f16_kernel<<<(n4o + 255) / 256, 256>>>(w_out, wouth, n4o);
    }

    // 1) QKV projection -> fp16 qkv
    gemm_f16<__half><<<dim3(3 * Eq / GT_N, Bq * Sq / GT_M), 512, GEMM_SMEM>>>(
        xh, wqkvh, qkv, Bq * Sq, 3 * Eq, Eq);

    // 2) fused RoPE + causal flash attention (fp16 mma)
    flash_attn_f16<<<dim3(Sq / 128, Bq * Hq), 256, FA_SMEM>>>(qkv, fcos, fsin, attn);

    // 3) output projection -> fp32 out
    gemm_f16<float><<<dim3(Eq / GT_N, Bq * Sq / GT_M), 512, GEMM_SMEM>>>(
        attn, wouth, out, Bq * Sq, Eq, Eq);
}

// round 10
// speedup vs baseline: 3.9390x; 1.1003x over previous
#include <cuda_runtime.h>
#include <cuda_bf16.h>
#include <cuda_fp16.h>
#include <mma.h>
#include <cstdint>
#include <type_traits>

using namespace nvcuda;

#define Bq 2
#define Sq 2048
#define Eq 1024
#define Hq 16
#define Dq 64

// Scratch buffers (no cudaMalloc allowed)
__device__ __half g_qkv[(size_t)Bq * Sq * 3 * Eq];    // [B*S, 3E] fp16
__device__ __half g_attn[(size_t)Bq * Sq * Eq];       // [B*S, E] fp16
__device__ __half g_xh[(size_t)Bq * Sq * Eq];         // fp16 x
__device__ __half g_wqkvh[(size_t)Eq * 3 * Eq];       // fp16 w_qkv
__device__ __half g_wouth[(size_t)Eq * Eq];           // fp16 w_out

// ---------------------------------------------------------------------------
// helpers
// ---------------------------------------------------------------------------
__device__ __forceinline__ void cp16(void* dst_smem, const void* src) {
    unsigned int d = (unsigned int)__cvta_generic_to_shared(dst_smem);
    asm volatile("cp.async.cg.shared.global [%0], [%1], 16;\n" :: "r"(d), "l"(src));
}
__device__ __forceinline__ void cp_commit() {
    asm volatile("cp.async.commit_group;\n");
}
template <int N> __device__ __forceinline__ void cp_wait() {
    asm volatile("cp.async.wait_group %0;\n" :: "n"(N));
}

// mma m16n8k16 fp16 inputs, f32 accum
__device__ __forceinline__ void mma_f16(float* d, const uint32_t* a,
                                        uint32_t b0, uint32_t b1) {
    asm volatile(
        "mma.sync.aligned.m16n8k16.row.col.f32.f16.f16.f32 "
        "{%0,%1,%2,%3}, {%4,%5,%6,%7}, {%8,%9}, {%0,%1,%2,%3};\n"
        : "+f"(d[0]), "+f"(d[1]), "+f"(d[2]), "+f"(d[3])
        : "r"(a[0]), "r"(a[1]), "r"(a[2]), "r"(a[3]), "r"(b0), "r"(b1));
}

__device__ __forceinline__ void ldsm_x4_trans(unsigned int addr,
    uint32_t& r0, uint32_t& r1, uint32_t& r2, uint32_t& r3) {
    asm volatile(
        "ldmatrix.sync.aligned.m8n8.x4.trans.shared.b16 {%0,%1,%2,%3}, [%4];\n"
        : "=r"(r0), "=r"(r1), "=r"(r2), "=r"(r3) : "r"(addr));
}

__device__ __forceinline__ uint32_t packh2(float lo, float hi) {
    __half2 h = __floats2half2_rn(lo, hi);
    return *(uint32_t*)&h;
}

// ---------------------------------------------------------------------------
// Elementwise f32 -> f16 conversion pass
// ---------------------------------------------------------------------------
__global__ void f32_to_f16_kernel(const float* __restrict__ src,
                                  __half* __restrict__ dst, int n4)
{
    int i = blockIdx.x * blockDim.x + threadIdx.x;
    if (i < n4) {
        float4 v = ((const float4*)src)[i];
        ((__half2*)dst)[2 * i]     = __floats2half2_rn(v.x, v.y);
        ((__half2*)dst)[2 * i + 1] = __floats2half2_rn(v.z, v.w);
    }
}

// ---------------------------------------------------------------------------
// FP16 GEMM (f32 accum): C[M,N] = A[M,K] @ B[K,N]. OutT = float or __half.
// 128x128x32 tile, 256 threads = 8 warps, warp grid 2(M)x4(N),
// 64x32 warp tile (4x2 wmma frags -> 8 mmas per 6 fragment loads).
// cp.async 3-stage pipeline.
// ---------------------------------------------------------------------------
#define GT_M 128
#define GT_N 128
#define GT_K 32
#define A_LDH 40
#define B_LDH 136
#define GA_SZ (GT_M * A_LDH)
#define GB_SZ (GT_K * B_LDH)
#define STAGE_SZ (GA_SZ + GB_SZ)
#define G_STAGES 3
#define GEMM_SMEM (G_STAGES * STAGE_SZ * sizeof(__half))   // 56832 B
#define C_STAGE_LD 20   // floats; multiple of 4 for wmma f32 store

template <typename OutT>
__global__ __launch_bounds__(256, 2) void gemm_f16(
    const __half* __restrict__ A, const __half* __restrict__ B,
    OutT* __restrict__ C, int M, int N, int K)
{
    extern __shared__ __half gsm[];

    const int tid = threadIdx.x;
    const int warp = tid >> 5;
    const int lane = tid & 31;
    const int wm = warp & 1;          // 64-row slab
    const int wn = warp >> 1;         // 32-col slab
    const int brow = blockIdx.y * GT_M;
    const int bcol = blockIdx.x * GT_N;

    // A: 128 rows x 32 halves; 256 thr x 8 halves x 2 passes
    const int arw = tid >> 2;            // 0..63 (+64)
    const int ac8 = (tid & 3) * 8;
    // B: 32 rows x 128 halves; 256 thr x 8 halves x 2 passes
    const int brw = tid >> 4;            // 0..15 (+16)
    const int bc8 = (tid & 15) * 8;

    wmma::fragment<wmma::accumulator, 16, 16, 16, float> c[4][2];
#pragma unroll
    for (int i = 0; i < 4; i++)
#pragma unroll
        for (int j = 0; j < 2; j++) wmma::fill_fragment(c[i][j], 0.f);

    const int T = K / GT_K;

    auto issue = [&](int t) {
        __half* dst = gsm + (t % G_STAGES) * STAGE_SZ;
        int k0 = t * GT_K;
#pragma unroll
        for (int p = 0; p < 2; p++)
            cp16(&dst[(arw + p * 64) * A_LDH + ac8],
                 &A[(size_t)(brow + arw + p * 64) * K + k0 + ac8]);
#pragma unroll
        for (int p = 0; p < 2; p++)
            cp16(&dst[GA_SZ + (brw + p * 16) * B_LDH + bc8],
                 &B[(size_t)(k0 + brw + p * 16) * N + bcol + bc8]);
        cp_commit();
    };

    issue(0);
    issue(1);

    for (int t = 0; t < T; t++) {
        cp_wait<G_STAGES - 2>();
        __syncthreads();

        if (t + G_STAGES - 1 < T) issue(t + G_STAGES - 1);

        __half* Ac = gsm + (t % G_STAGES) * STAGE_SZ;
        __half* Bc = Ac + GA_SZ;
#pragma unroll
        for (int kk = 0; kk < GT_K; kk += 16) {
            wmma::fragment<wmma::matrix_a, 16, 16, 16, __half, wmma::row_major> a[4];
            wmma::fragment<wmma::matrix_b, 16, 16, 16, __half, wmma::row_major> bf[2];
#pragma unroll
            for (int i = 0; i < 4; i++)
                wmma::load_matrix_sync(a[i], &Ac[(wm * 64 + i * 16) * A_LDH + kk], A_LDH);
#pragma unroll
            for (int j = 0; j < 2; j++)
                wmma::load_matrix_sync(bf[j], &Bc[kk * B_LDH + wn * 32 + j * 16], B_LDH);
#pragma unroll
            for (int i = 0; i < 4; i++)
#pragma unroll
                for (int j = 0; j < 2; j++)
                    wmma::mma_sync(c[i][j], a[i], bf[j], c[i][j]);
        }
        __syncthreads();
    }

    if constexpr (std::is_same<OutT, float>::value) {
#pragma unroll
        for (int i = 0; i < 4; i++)
#pragma unroll
            for (int j = 0; j < 2; j++)
                wmma::store_matrix_sync(
                    &C[(size_t)(brow + wm * 64 + i * 16) * N + bcol + wn * 32 + j * 16],
                    c[i][j], N, wmma::mem_row_major);
    } else {
        // stage f32 c-frags through smem, emit fp16 (per-warp region, ld=20)
        float* stage = (float*)gsm + warp * (16 * C_STAGE_LD);
        const int r = lane >> 1;
        const int c0 = (lane & 1) * 8;
#pragma unroll
        for (int i = 0; i < 4; i++)
#pragma unroll
            for (int j = 0; j < 2; j++) {
                wmma::store_matrix_sync(stage, c[i][j], C_STAGE_LD,
                                        wmma::mem_row_major);
                __syncwarp();
                const float* sp = stage + r * C_STAGE_LD + c0;
                __half2 h[4];
#pragma unroll
                for (int q = 0; q < 4; q++)
                    h[q] = __floats2half2_rn(sp[2 * q], sp[2 * q + 1]);
                *(uint4*)&C[(size_t)(brow + wm * 64 + i * 16 + r) * N +
                            bcol + wn * 32 + j * 16 + c0] = *(uint4*)h;
                __syncwarp();
            }
    }
}

// ---------------------------------------------------------------------------
// Register-resident flash attention, fp16 mma m16n8k16 (unchanged from R9).
// ---------------------------------------------------------------------------
#define QLDH 72
#define KLDH 72
#define VLDH 72
#define FA_SMEM (128 * QLDH * sizeof(__half))   // 18432 B

__global__ __launch_bounds__(256, 2) void flash_attn_f16(
    const __half* __restrict__ qkv,
    const float* __restrict__ fcos, const float* __restrict__ fsin,
    __half* __restrict__ attn)
{
    extern __shared__ __half smh[];
    __half* Ks = smh;
    __half* Vs = smh + 64 * KLDH;
    __half* Qstage = smh;

    const int tid  = threadIdx.x;
    const int lane = tid & 31;
    const int wr   = tid >> 5;
    const int g    = lane >> 2;
    const int j    = lane & 3;
    const int qi   = blockIdx.x;
    const int b    = blockIdx.y >> 4;
    const int h    = blockIdx.y & 15;
    const int qbase = qi * 128;
    const size_t rs3 = 3 * Eq;
    const size_t base = (size_t)b * Sq * rs3 + (size_t)h * Dq;

    for (int t = tid; t < 128 * 32; t += 256) {
        int r = t >> 5, pr = t & 31;
        int sg = qbase + r;
        float2 xv = __half22float2(*(const __half2*)&qkv[base + (size_t)sg * rs3 + 2 * pr]);
        float c = fcos[sg * 32 + pr], sn = fsin[sg * 32 + pr];
        *(__half2*)&Qstage[r * QLDH + 2 * pr] =
            __floats2half2_rn((xv.x * c - xv.y * sn) * 0.125f,
                              (xv.x * sn + xv.y * c) * 0.125f);
    }
    __syncthreads();

    uint32_t qa[4][4];
    {
        const int r0 = wr * 16 + g;
#pragma unroll
        for (int kc = 0; kc < 4; kc++) {
            int col = kc * 16 + 2 * j;
            qa[kc][0] = *(const uint32_t*)&Qstage[r0 * QLDH + col];
            qa[kc][1] = *(const uint32_t*)&Qstage[(r0 + 8) * QLDH + col];
            qa[kc][2] = *(const uint32_t*)&Qstage[r0 * QLDH + col + 8];
            qa[kc][3] = *(const uint32_t*)&Qstage[(r0 + 8) * QLDH + col + 8];
        }
    }
    __syncthreads();

    float od[8][4];
#pragma unroll
    for (int n = 0; n < 8; n++)
#pragma unroll
        for (int i = 0; i < 4; i++) od[n][i] = 0.f;

    float m0 = -1e30f, m1 = -1e30f, l0 = 0.f, l1 = 0.f;

    const int wq_lo = qbase + wr * 16;
    const int wq_hi = wq_lo + 15;
    const int r0g = wq_lo + g;
    const int r1g = r0g + 8;
    const int ntiles = 2 * qi + 2;

    const int lm_m  = lane >> 3;
    const int lm_rr = lane & 7;
    const int lm_keyoff = (lm_m & 1) * 8 + lm_rr;
    const int lm_dimoff = (lm_m >> 1) * 8;

    for (int kt = 0; kt < ntiles; ++kt) {
        const int kbase = kt * 64;

        for (int t = tid; t < 64 * 32; t += 256) {
            int r = t >> 5, pr = t & 31;
            int sg = kbase + r;
            float2 xv = __half22float2(
                *(const __half2*)&qkv[base + Eq + (size_t)sg * rs3 + 2 * pr]);
            float c = fcos[sg * 32 + pr], sn = fsin[sg * 32 + pr];
            *(__half2*)&Ks[r * KLDH + 2 * pr] =
                __floats2half2_rn(xv.x * c - xv.y * sn, xv.x * sn + xv.y * c);
        }
        for (int t = tid; t < 64 * 16; t += 256) {
            int r = t >> 4, c4 = (t & 15) * 4;
            *(uint2*)&Vs[r * VLDH + c4] =
                *(const uint2*)&qkv[base + 2 * Eq + (size_t)(kbase + r) * rs3 + c4];
        }
        __syncthreads();

        if (kbase <= wq_hi) {
            float s[8][4];
#pragma unroll
            for (int nc = 0; nc < 8; nc++) {
                s[nc][0] = s[nc][1] = s[nc][2] = s[nc][3] = 0.f;
                const __half* krow = &Ks[(nc * 8 + g) * KLDH + 2 * j];
#pragma unroll
                for (int kc = 0; kc < 4; kc++) {
                    uint32_t kb0 = *(const uint32_t*)&krow[kc * 16];
                    uint32_t kb1 = *(const uint32_t*)&krow[kc * 16 + 8];
                    mma_f16(s[nc], qa[kc], kb0, kb1);
                }
            }

            if (kbase + 63 > wq_lo) {
#pragma unroll
                for (int nc = 0; nc < 8; nc++) {
                    int c0 = kbase + nc * 8 + 2 * j;
                    if (c0 > r0g)     s[nc][0] = -1e30f;
                    if (c0 + 1 > r0g) s[nc][1] = -1e30f;
                    if (c0 > r1g)     s[nc][2] = -1e30f;
                    if (c0 + 1 > r1g) s[nc][3] = -1e30f;
                }
            }

            float mx0 = -1e30f, mx1 = -1e30f;
#pragma unroll
            for (int nc = 0; nc < 8; nc++) {
                mx0 = fmaxf(mx0, fmaxf(s[nc][0], s[nc][1]));
                mx1 = fmaxf(mx1, fmaxf(s[nc][2], s[nc][3]));
            }
            mx0 = fmaxf(mx0, __shfl_xor_sync(0xffffffffu, mx0, 1));
            mx0 = fmaxf(mx0, __shfl_xor_sync(0xffffffffu, mx0, 2));
            mx1 = fmaxf(mx1, __shfl_xor_sync(0xffffffffu, mx1, 1));
            mx1 = fmaxf(mx1, __shfl_xor_sync(0xffffffffu, mx1, 2));

            float mn0 = fmaxf(m0, mx0);
            float mn1 = fmaxf(m1, mx1);
            float corr0 = __expf(m0 - mn0);
            float corr1 = __expf(m1 - mn1);
            m0 = mn0; m1 = mn1;

            float sum0 = 0.f, sum1 = 0.f;
#pragma unroll
            for (int nc = 0; nc < 8; nc++) {
                s[nc][0] = __expf(s[nc][0] - mn0);
                s[nc][1] = __expf(s[nc][1] - mn0);
                s[nc][2] = __expf(s[nc][2] - mn1);
                s[nc][3] = __expf(s[nc][3] - mn1);
                sum0 += s[nc][0] + s[nc][1];
                sum1 += s[nc][2] + s[nc][3];
            }
            sum0 += __shfl_xor_sync(0xffffffffu, sum0, 1);
            sum0 += __shfl_xor_sync(0xffffffffu, sum0, 2);
            sum1 += __shfl_xor_sync(0xffffffffu, sum1, 1);
            sum1 += __shfl_xor_sync(0xffffffffu, sum1, 2);
            l0 = l0 * corr0 + sum0;
            l1 = l1 * corr1 + sum1;

#pragma unroll
            for (int n = 0; n < 8; n++) {
                od[n][0] *= corr0; od[n][1] *= corr0;
                od[n][2] *= corr1; od[n][3] *= corr1;
            }

            uint32_t pa[4][4];
#pragma unroll
            for (int kc = 0; kc < 4; kc++) {
                pa[kc][0] = packh2(s[2 * kc][0],     s[2 * kc][1]);
                pa[kc][1] = packh2(s[2 * kc][2],     s[2 * kc][3]);
                pa[kc][2] = packh2(s[2 * kc + 1][0], s[2 * kc + 1][1]);
                pa[kc][3] = packh2(s[2 * kc + 1][2], s[2 * kc + 1][3]);
            }

#pragma unroll
            for (int nd2 = 0; nd2 < 4; nd2++) {
#pragma unroll
                for (int kc = 0; kc < 4; kc++) {
                    unsigned int addr = (unsigned int)__cvta_generic_to_shared(
                        &Vs[(kc * 16 + lm_keyoff) * VLDH + nd2 * 16 + lm_dimoff]);
                    uint32_t b0, b1, b2, b3;
                    ldsm_x4_trans(addr, b0, b1, b2, b3);
                    mma_f16(od[2 * nd2],     pa[kc], b0, b1);
                    mma_f16(od[2 * nd2 + 1], pa[kc], b2, b3);
                }
            }
        }
        __syncthreads();
    }

    {
        float inv0 = 1.f / l0;
        float inv1 = 1.f / l1;
        __half* op0 = &attn[((size_t)b * Sq + r0g) * Eq + h * Dq];
        __half* op1 = &attn[((size_t)b * Sq + r1g) * Eq + h * Dq];
#pragma unroll
        for (int nd = 0; nd < 8; nd++) {
            int c0 = nd * 8 + 2 * j;
            *(__half2*)&op0[c0] = __floats2half2_rn(od[nd][0] * inv0, od[nd][1] * inv0);
            *(__half2*)&op1[c0] = __floats2half2_rn(od[nd][2] * inv1, od[nd][3] * inv1);
        }
    }
}

// ---------------------------------------------------------------------------
extern "C" void kernel_launch(void* const* d_in, const int* in_sizes, int n_in,
                              void* d_out, int out_size)
{
    const float* x     = (const float*)d_in[0];
    const float* w_qkv = (const float*)d_in[1];
    const float* w_out = (const float*)d_in[2];
    const float* fcos  = (const float*)d_in[3];
    const float* fsin  = (const float*)d_in[4];
    float* out = (float*)d_out;

    __half *qkv, *attn, *xh, *wqkvh, *wouth;
    cudaGetSymbolAddress((void**)&qkv, g_qkv);
    cudaGetSymbolAddress((void**)&attn, g_attn);
    cudaGetSymbolAddress((void**)&xh, g_xh);
    cudaGetSymbolAddress((void**)&wqkvh, g_wqkvh);
    cudaGetSymbolAddress((void**)&wouth, g_wouth);

    cudaFuncSetAttribute(gemm_f16<__half>,
                         cudaFuncAttributeMaxDynamicSharedMemorySize, GEMM_SMEM);
    cudaFuncSetAttribute(gemm_f16<float>,
                         cudaFuncAttributeMaxDynamicSharedMemorySize, GEMM_SMEM);

    // 0) fp16 conversion of GEMM inputs
    {
        int n4x = Bq * Sq * Eq / 4;
        int n4q = Eq * 3 * Eq / 4;
        int n4o = Eq * Eq / 4;
        f32_to_f16_kernel<<<(n4x + 255) / 256, 256>>>(x, xh, n4x);
        f32_to_f16_kernel<<<(n4q + 255) / 256, 256>>>(w_qkv, wqkvh, n4q);
        f32_to_f16_kernel<<<(n4o + 255) / 256, 256>>>(w_out, wouth, n4o);
    }

    // 1) QKV projection -> fp16 qkv
    gemm_f16<__half><<<dim3(3 * Eq / GT_N, Bq * Sq / GT_M), 256, GEMM_SMEM>>>(
        xh, wqkvh, qkv, Bq * Sq, 3 * Eq, Eq);

    // 2) fused RoPE + causal flash attention (fp16 mma)
    flash_attn_f16<<<dim3(Sq / 128, Bq * Hq), 256, FA_SMEM>>>(qkv, fcos, fsin, attn);

    // 3) output projection -> fp32 out
    gemm_f16<float><<<dim3(Eq / GT_N, Bq * Sq / GT_M), 256, GEMM_SMEM>>>(
        attn, wouth, out, Bq * Sq, Eq, Eq);
}

// round 11
// speedup vs baseline: 5.0643x; 1.2857x over previous
#include <cuda_runtime.h>
#include <cuda_bf16.h>
#include <cuda_fp16.h>
#include <mma.h>
#include <cstdint>
#include <type_traits>

using namespace nvcuda;

#define Bq 2
#define Sq 2048
#define Eq 1024
#define Hq 16
#define Dq 64

// Scratch buffers (no cudaMalloc allowed)
__device__ __half g_qkv[(size_t)Bq * Sq * 3 * Eq];    // [B*S, 3E] fp16
__device__ __half g_attn[(size_t)Bq * Sq * Eq];       // [B*S, E] fp16
__device__ __half g_xh[(size_t)Bq * Sq * Eq];         // fp16 x
__device__ __half g_wqkvh[(size_t)Eq * 3 * Eq];       // fp16 w_qkv
__device__ __half g_wouth[(size_t)Eq * Eq];           // fp16 w_out

// ---------------------------------------------------------------------------
// helpers
// ---------------------------------------------------------------------------
__device__ __forceinline__ void cp16(void* dst_smem, const void* src) {
    unsigned int d = (unsigned int)__cvta_generic_to_shared(dst_smem);
    asm volatile("cp.async.cg.shared.global [%0], [%1], 16;\n" :: "r"(d), "l"(src));
}
__device__ __forceinline__ void cp_commit() {
    asm volatile("cp.async.commit_group;\n");
}
template <int N> __device__ __forceinline__ void cp_wait() {
    asm volatile("cp.async.wait_group %0;\n" :: "n"(N));
}

// mma m16n8k16 fp16 inputs, f32 accum
__device__ __forceinline__ void mma_f16(float* d, const uint32_t* a,
                                        uint32_t b0, uint32_t b1) {
    asm volatile(
        "mma.sync.aligned.m16n8k16.row.col.f32.f16.f16.f32 "
        "{%0,%1,%2,%3}, {%4,%5,%6,%7}, {%8,%9}, {%0,%1,%2,%3};\n"
        : "+f"(d[0]), "+f"(d[1]), "+f"(d[2]), "+f"(d[3])
        : "r"(a[0]), "r"(a[1]), "r"(a[2]), "r"(a[3]), "r"(b0), "r"(b1));
}

__device__ __forceinline__ void ldsm_x4_trans(unsigned int addr,
    uint32_t& r0, uint32_t& r1, uint32_t& r2, uint32_t& r3) {
    asm volatile(
        "ldmatrix.sync.aligned.m8n8.x4.trans.shared.b16 {%0,%1,%2,%3}, [%4];\n"
        : "=r"(r0), "=r"(r1), "=r"(r2), "=r"(r3) : "r"(addr));
}

__device__ __forceinline__ uint32_t packh2(float lo, float hi) {
    __half2 h = __floats2half2_rn(lo, hi);
    return *(uint32_t*)&h;
}

// ---------------------------------------------------------------------------
// Elementwise f32 -> f16 conversion pass
// ---------------------------------------------------------------------------
__global__ void f32_to_f16_kernel(const float* __restrict__ src,
                                  __half* __restrict__ dst, int n4)
{
    int i = blockIdx.x * blockDim.x + threadIdx.x;
    if (i < n4) {
        float4 v = ((const float4*)src)[i];
        ((__half2*)dst)[2 * i]     = __floats2half2_rn(v.x, v.y);
        ((__half2*)dst)[2 * i + 1] = __floats2half2_rn(v.z, v.w);
    }
}

// ---------------------------------------------------------------------------
// In-place RoPE on Q (with 0.125 pre-scale) and K inside g_qkv.
// One thread per rotation pair. i decomposes as b|s|h|pair.
// ---------------------------------------------------------------------------
__global__ void rope_qk_kernel(__half* __restrict__ qkv,
                               const float* __restrict__ fcos,
                               const float* __restrict__ fsin)
{
    int i = blockIdx.x * blockDim.x + threadIdx.x;   // 0 .. B*S*E/2-1
    if (i >= Bq * Sq * Eq / 2) return;
    int pr = i & 31;
    int hh = (i >> 5) & 15;
    int s  = (i >> 9) & (Sq - 1);
    int bb = i >> 20;                                // Sq*Eq/2 = 2^20
    size_t off = ((size_t)(bb * Sq + s)) * (3 * Eq) + hh * Dq + 2 * pr;
    float c = fcos[s * 32 + pr], sn = fsin[s * 32 + pr];

    float2 q = __half22float2(*(__half2*)&qkv[off]);
    *(__half2*)&qkv[off] =
        __floats2half2_rn((q.x * c - q.y * sn) * 0.125f,
                          (q.x * sn + q.y * c) * 0.125f);

    float2 k = __half22float2(*(__half2*)&qkv[off + Eq]);
    *(__half2*)&qkv[off + Eq] =
        __floats2half2_rn(k.x * c - k.y * sn, k.x * sn + k.y * c);
}

// ---------------------------------------------------------------------------
// FP16 GEMM (f32 accum): 128x128x32, 256 threads, 64x32 warp tile,
// cp.async 3-stage pipeline. (unchanged from R10)
// ---------------------------------------------------------------------------
#define GT_M 128
#define GT_N 128
#define GT_K 32
#define A_LDH 40
#define B_LDH 136
#define GA_SZ (GT_M * A_LDH)
#define GB_SZ (GT_K * B_LDH)
#define STAGE_SZ (GA_SZ + GB_SZ)
#define G_STAGES 3
#define GEMM_SMEM (G_STAGES * STAGE_SZ * sizeof(__half))   // 56832 B
#define C_STAGE_LD 20

template <typename OutT>
__global__ __launch_bounds__(256, 2) void gemm_f16(
    const __half* __restrict__ A, const __half* __restrict__ B,
    OutT* __restrict__ C, int M, int N, int K)
{
    extern __shared__ __half gsm[];

    const int tid = threadIdx.x;
    const int warp = tid >> 5;
    const int lane = tid & 31;
    const int wm = warp & 1;
    const int wn = warp >> 1;
    const int brow = blockIdx.y * GT_M;
    const int bcol = blockIdx.x * GT_N;

    const int arw = tid >> 2;
    const int ac8 = (tid & 3) * 8;
    const int brw = tid >> 4;
    const int bc8 = (tid & 15) * 8;

    wmma::fragment<wmma::accumulator, 16, 16, 16, float> c[4][2];
#pragma unroll
    for (int i = 0; i < 4; i++)
#pragma unroll
        for (int j = 0; j < 2; j++) wmma::fill_fragment(c[i][j], 0.f);

    const int T = K / GT_K;

    auto issue = [&](int t) {
        __half* dst = gsm + (t % G_STAGES) * STAGE_SZ;
        int k0 = t * GT_K;
#pragma unroll
        for (int p = 0; p < 2; p++)
            cp16(&dst[(arw + p * 64) * A_LDH + ac8],
                 &A[(size_t)(brow + arw + p * 64) * K + k0 + ac8]);
#pragma unroll
        for (int p = 0; p < 2; p++)
            cp16(&dst[GA_SZ + (brw + p * 16) * B_LDH + bc8],
                 &B[(size_t)(k0 + brw + p * 16) * N + bcol + bc8]);
        cp_commit();
    };

    issue(0);
    issue(1);

    for (int t = 0; t < T; t++) {
        cp_wait<G_STAGES - 2>();
        __syncthreads();

        if (t + G_STAGES - 1 < T) issue(t + G_STAGES - 1);

        __half* Ac = gsm + (t % G_STAGES) * STAGE_SZ;
        __half* Bc = Ac + GA_SZ;
#pragma unroll
        for (int kk = 0; kk < GT_K; kk += 16) {
            wmma::fragment<wmma::matrix_a, 16, 16, 16, __half, wmma::row_major> a[4];
            wmma::fragment<wmma::matrix_b, 16, 16, 16, __half, wmma::row_major> bf[2];
#pragma unroll
            for (int i = 0; i < 4; i++)
                wmma::load_matrix_sync(a[i], &Ac[(wm * 64 + i * 16) * A_LDH + kk], A_LDH);
#pragma unroll
            for (int j = 0; j < 2; j++)
                wmma::load_matrix_sync(bf[j], &Bc[kk * B_LDH + wn * 32 + j * 16], B_LDH);
#pragma unroll
            for (int i = 0; i < 4; i++)
#pragma unroll
                for (int j = 0; j < 2; j++)
                    wmma::mma_sync(c[i][j], a[i], bf[j], c[i][j]);
        }
        __syncthreads();
    }

    if constexpr (std::is_same<OutT, float>::value) {
#pragma unroll
        for (int i = 0; i < 4; i++)
#pragma unroll
            for (int j = 0; j < 2; j++)
                wmma::store_matrix_sync(
                    &C[(size_t)(brow + wm * 64 + i * 16) * N + bcol + wn * 32 + j * 16],
                    c[i][j], N, wmma::mem_row_major);
    } else {
        float* stage = (float*)gsm + warp * (16 * C_STAGE_LD);
        const int r = lane >> 1;
        const int c0 = (lane & 1) * 8;
#pragma unroll
        for (int i = 0; i < 4; i++)
#pragma unroll
            for (int j = 0; j < 2; j++) {
                wmma::store_matrix_sync(stage, c[i][j], C_STAGE_LD,
                                        wmma::mem_row_major);
                __syncwarp();
                const float* sp = stage + r * C_STAGE_LD + c0;
                __half2 h[4];
#pragma unroll
                for (int q = 0; q < 4; q++)
                    h[q] = __floats2half2_rn(sp[2 * q], sp[2 * q + 1]);
                *(uint4*)&C[(size_t)(brow + wm * 64 + i * 16 + r) * N +
                            bcol + wn * 32 + j * 16 + c0] = *(uint4*)h;
                __syncwarp();
            }
    }
}

// ---------------------------------------------------------------------------
// Register-resident flash attention, fp16 mma m16n8k16.
// Q/K already RoPE'd in gmem -> K/V fills are pure cp.async copies,
// double-buffered (tile kt+1 issued before computing tile kt).
// ---------------------------------------------------------------------------
#define QLDH 72
#define KLDH 72
#define VLDH 72
#define KV_SZ (64 * KLDH)                    // halves per K (or V) buffer
#define FA_SMEM (4 * KV_SZ * sizeof(__half)) // 2 x (K+V) = 36864 B

__global__ __launch_bounds__(256, 2) void flash_attn_f16(
    const __half* __restrict__ qkv,
    __half* __restrict__ attn)
{
    extern __shared__ __half smh[];
    // buffers: [K0][V0][K1][V1]; Qstage overlaps the front (used first)
    __half* Qstage = smh;                    // [128][QLDH] = 9216 halves

    const int tid  = threadIdx.x;
    const int lane = tid & 31;
    const int wr   = tid >> 5;
    const int g    = lane >> 2;
    const int j    = lane & 3;
    const int qi   = blockIdx.x;
    const int b    = blockIdx.y >> 4;
    const int h    = blockIdx.y & 15;
    const int qbase = qi * 128;
    const size_t rs3 = 3 * Eq;
    const size_t base = (size_t)b * Sq * rs3 + (size_t)h * Dq;

    // ---- stage Q (straight copy; already RoPE'd + scaled) ----
    for (int t = tid; t < 128 * 8; t += 256) {
        int r = t >> 3, c8 = (t & 7) * 8;
        *(uint4*)&Qstage[r * QLDH + c8] =
            *(const uint4*)&qkv[base + (size_t)(qbase + r) * rs3 + c8];
    }
    __syncthreads();

    uint32_t qa[4][4];
    {
        const int r0 = wr * 16 + g;
#pragma unroll
        for (int kc = 0; kc < 4; kc++) {
            int col = kc * 16 + 2 * j;
            qa[kc][0] = *(const uint32_t*)&Qstage[r0 * QLDH + col];
            qa[kc][1] = *(const uint32_t*)&Qstage[(r0 + 8) * QLDH + col];
            qa[kc][2] = *(const uint32_t*)&Qstage[r0 * QLDH + col + 8];
            qa[kc][3] = *(const uint32_t*)&Qstage[(r0 + 8) * QLDH + col + 8];
        }
    }
    __syncthreads();   // Qstage region about to be reused as K/V buffers

    float od[8][4];
#pragma unroll
    for (int n = 0; n < 8; n++)
#pragma unroll
        for (int i = 0; i < 4; i++) od[n][i] = 0.f;

    float m0 = -1e30f, m1 = -1e30f, l0 = 0.f, l1 = 0.f;

    const int wq_lo = qbase + wr * 16;
    const int wq_hi = wq_lo + 15;
    const int r0g = wq_lo + g;
    const int r1g = r0g + 8;
    const int ntiles = 2 * qi + 2;

    const int lm_m  = lane >> 3;
    const int lm_rr = lane & 7;
    const int lm_keyoff = (lm_m & 1) * 8 + lm_rr;
    const int lm_dimoff = (lm_m >> 1) * 8;

    // pure-copy cp.async tile fill: K + V = 1024 16B chunks, 4 per thread
    auto issue_tile = [&](int kt) {
        __half* kd = smh + (kt & 1) * 2 * KV_SZ;
        __half* vd = kd + KV_SZ;
        const int kb = kt * 64;
#pragma unroll
        for (int p = 0; p < 2; p++) {
            int t = tid + p * 256;         // 0..511
            int r = t >> 3, c8 = (t & 7) * 8;
            cp16(&kd[r * KLDH + c8],
                 &qkv[base + Eq + (size_t)(kb + r) * rs3 + c8]);
        }
#pragma unroll
        for (int p = 0; p < 2; p++) {
            int t = tid + p * 256;
            int r = t >> 3, c8 = (t & 7) * 8;
            cp16(&vd[r * VLDH + c8],
                 &qkv[base + 2 * Eq + (size_t)(kb + r) * rs3 + c8]);
        }
        cp_commit();
    };

    issue_tile(0);

    for (int kt = 0; kt < ntiles; ++kt) {
        if (kt + 1 < ntiles) {
            issue_tile(kt + 1);
            cp_wait<1>();
        } else {
            cp_wait<0>();
        }
        __syncthreads();

        const __half* Ks = smh + (kt & 1) * 2 * KV_SZ;
        const __half* Vs = Ks + KV_SZ;
        const int kbase = kt * 64;

        if (kbase <= wq_hi) {
            // ---- S = Q @ K^T ----
            float s[8][4];
#pragma unroll
            for (int nc = 0; nc < 8; nc++) {
                s[nc][0] = s[nc][1] = s[nc][2] = s[nc][3] = 0.f;
                const __half* krow = &Ks[(nc * 8 + g) * KLDH + 2 * j];
#pragma unroll
                for (int kc = 0; kc < 4; kc++) {
                    uint32_t kb0 = *(const uint32_t*)&krow[kc * 16];
                    uint32_t kb1 = *(const uint32_t*)&krow[kc * 16 + 8];
                    mma_f16(s[nc], qa[kc], kb0, kb1);
                }
            }

            // ---- causal mask ----
            if (kbase + 63 > wq_lo) {
#pragma unroll
                for (int nc = 0; nc < 8; nc++) {
                    int c0 = kbase + nc * 8 + 2 * j;
                    if (c0 > r0g)     s[nc][0] = -1e30f;
                    if (c0 + 1 > r0g) s[nc][1] = -1e30f;
                    if (c0 > r1g)     s[nc][2] = -1e30f;
                    if (c0 + 1 > r1g) s[nc][3] = -1e30f;
                }
            }

            // ---- online softmax ----
            float mx0 = -1e30f, mx1 = -1e30f;
#pragma unroll
            for (int nc = 0; nc < 8; nc++) {
                mx0 = fmaxf(mx0, fmaxf(s[nc][0], s[nc][1]));
                mx1 = fmaxf(mx1, fmaxf(s[nc][2], s[nc][3]));
            }
            mx0 = fmaxf(mx0, __shfl_xor_sync(0xffffffffu, mx0, 1));
            mx0 = fmaxf(mx0, __shfl_xor_sync(0xffffffffu, mx0, 2));
            mx1 = fmaxf(mx1, __shfl_xor_sync(0xffffffffu, mx1, 1));
            mx1 = fmaxf(mx1, __shfl_xor_sync(0xffffffffu, mx1, 2));

            float mn0 = fmaxf(m0, mx0);
            float mn1 = fmaxf(m1, mx1);
            float corr0 = __expf(m0 - mn0);
            float corr1 = __expf(m1 - mn1);
            m0 = mn0; m1 = mn1;

            float sum0 = 0.f, sum1 = 0.f;
#pragma unroll
            for (int nc = 0; nc < 8; nc++) {
                s[nc][0] = __expf(s[nc][0] - mn0);
                s[nc][1] = __expf(s[nc][1] - mn0);
                s[nc][2] = __expf(s[nc][2] - mn1);
                s[nc][3] = __expf(s[nc][3] - mn1);
                sum0 += s[nc][0] + s[nc][1];
                sum1 += s[nc][2] + s[nc][3];
            }
            sum0 += __shfl_xor_sync(0xffffffffu, sum0, 1);
            sum0 += __shfl_xor_sync(0xffffffffu, sum0, 2);
            sum1 += __shfl_xor_sync(0xffffffffu, sum1, 1);
            sum1 += __shfl_xor_sync(0xffffffffu, sum1, 2);
            l0 = l0 * corr0 + sum0;
            l1 = l1 * corr1 + sum1;

#pragma unroll
            for (int n = 0; n < 8; n++) {
                od[n][0] *= corr0; od[n][1] *= corr0;
                od[n][2] *= corr1; od[n][3] *= corr1;
            }

            // ---- P c-frags -> fp16 a-frags (layouts match) ----
            uint32_t pa[4][4];
#pragma unroll
            for (int kc = 0; kc < 4; kc++) {
                pa[kc][0] = packh2(s[2 * kc][0],     s[2 * kc][1]);
                pa[kc][1] = packh2(s[2 * kc][2],     s[2 * kc][3]);
                pa[kc][2] = packh2(s[2 * kc + 1][0], s[2 * kc + 1][1]);
                pa[kc][3] = packh2(s[2 * kc + 1][2], s[2 * kc + 1][3]);
            }

            // ---- O += P @ V ----
#pragma unroll
            for (int nd2 = 0; nd2 < 4; nd2++) {
#pragma unroll
                for (int kc = 0; kc < 4; kc++) {
                    unsigned int addr = (unsigned int)__cvta_generic_to_shared(
                        &Vs[(kc * 16 + lm_keyoff) * VLDH + nd2 * 16 + lm_dimoff]);
                    uint32_t b0, b1, b2, b3;
                    ldsm_x4_trans(addr, b0, b1, b2, b3);
                    mma_f16(od[2 * nd2],     pa[kc], b0, b1);
                    mma_f16(od[2 * nd2 + 1], pa[kc], b2, b3);
                }
            }
        }
        __syncthreads();   // all warps done with buf[kt&1] before it's refilled
    }

    // ---- epilogue ----
    {
        float inv0 = 1.f / l0;
        float inv1 = 1.f / l1;
        __half* op0 = &attn[((size_t)b * Sq + r0g) * Eq + h * Dq];
        __half* op1 = &attn[((size_t)b * Sq + r1g) * Eq + h * Dq];
#pragma unroll
        for (int nd = 0; nd < 8; nd++) {
            int c0 = nd * 8 + 2 * j;
            *(__half2*)&op0[c0] = __floats2half2_rn(od[nd][0] * inv0, od[nd][1] * inv0);
            *(__half2*)&op1[c0] = __floats2half2_rn(od[nd][2] * inv1, od[nd][3] * inv1);
        }
    }
}

// ---------------------------------------------------------------------------
extern "C" void kernel_launch(void* const* d_in, const int* in_sizes, int n_in,
                              void* d_out, int out_size)
{
    const float* x     = (const float*)d_in[0];
    const float* w_qkv = (const float*)d_in[1];
    const float* w_out = (const float*)d_in[2];
    const float* fcos  = (const float*)d_in[3];
    const float* fsin  = (const float*)d_in[4];
    float* out = (float*)d_out;

    __half *qkv, *attn, *xh, *wqkvh, *wouth;
    cudaGetSymbolAddress((void**)&qkv, g_qkv);
    cudaGetSymbolAddress((void**)&attn, g_attn);
    cudaGetSymbolAddress((void**)&xh, g_xh);
    cudaGetSymbolAddress((void**)&wqkvh, g_wqkvh);
    cudaGetSymbolAddress((void**)&wouth, g_wouth);

    cudaFuncSetAttribute(gemm_f16<__half>,
                         cudaFuncAttributeMaxDynamicSharedMemorySize, GEMM_SMEM);
    cudaFuncSetAttribute(gemm_f16<float>,
                         cudaFuncAttributeMaxDynamicSharedMemorySize, GEMM_SMEM);
    cudaFuncSetAttribute(flash_attn_f16,
                         cudaFuncAttributeMaxDynamicSharedMemorySize, FA_SMEM);

    // 0) fp16 conversion of GEMM inputs
    {
        int n4x = Bq * Sq * Eq / 4;
        int n4q = Eq * 3 * Eq / 4;
        int n4o = Eq * Eq / 4;
        f32_to_f16_kernel<<<(n4x + 255) / 256, 256>>>(x, xh, n4x);
        f32_to_f16_kernel<<<(n4q + 255) / 256, 256>>>(w_qkv, wqkvh, n4q);
        f32_to_f16_kernel<<<(n4o + 255) / 256, 256>>>(w_out, wouth, n4o);
    }

    // 1) QKV projection -> fp16 qkv
    gemm_f16<__half><<<dim3(3 * Eq / GT_N, Bq * Sq / GT_M), 256, GEMM_SMEM>>>(
        xh, wqkvh, qkv, Bq * Sq, 3 * Eq, Eq);

    // 1b) in-place RoPE on Q (pre-scaled) and K
    {
        int n = Bq * Sq * Eq / 2;
        rope_qk_kernel<<<(n + 255) / 256, 256>>>(qkv, fcos, fsin);
    }

    // 2) causal flash attention (fp16 mma, double-buffered cp.async K/V)
    flash_attn_f16<<<dim3(Sq / 128, Bq * Hq), 256, FA_SMEM>>>(qkv, attn);

    // 3) output projection -> fp32 out
    gemm_f16<float><<<dim3(Eq / GT_N, Bq * Sq / GT_M), 256, GEMM_SMEM>>>(
        attn, wouth, out, Bq * Sq, Eq, Eq);
}